// round 11
// baseline (speedup 1.0000x reference)
#include <cuda_runtime.h>
#include <cuda_fp16.h>
#include <cstdint>

#define NH    16
#define HD    128
#define SEQ   2048
#define BATCH 2
#define HID   2048
#define MTOT  (BATCH * SEQ)   // 4096
#define GK    2048
#define LOG2E 1.4426950408889634f

// ---------------------------------------------------------------------------
// Scratch (__device__ globals — allocation-free)
// ---------------------------------------------------------------------------
__device__ __half g_Q [(size_t)BATCH * NH * SEQ * HD];  // Q [b,h,s,d]
__device__ __half g_K [(size_t)BATCH * NH * SEQ * HD];  // K [b,h,s,d]
__device__ __half g_Vt[(size_t)BATCH * NH * HD * SEQ];  // V [b,h,d,s]

__device__ __half g_A [(size_t)MTOT * HID];      // GEMM A (hidden / attn-out)
__device__ __half g_Wq[(size_t)3 * HID * HID];   // w_qkv^T fp16 [N,K]
__device__ __half g_Wp[(size_t)HID * HID];       // w_proj^T fp16 [N,K]

// ---------------------------------------------------------------------------
// helpers
// ---------------------------------------------------------------------------
__device__ __forceinline__ uint32_t smem_u32(const void* p) {
    uint32_t a;
    asm("{ .reg .u64 t; cvta.to.shared.u64 t, %1; cvt.u32.u64 %0, t; }"
        : "=r"(a) : "l"(p));
    return a;
}
__device__ __forceinline__ void cp_async16(uint32_t dst, const void* src) {
    asm volatile("cp.async.cg.shared.global [%0], [%1], 16;\n"
                 :: "r"(dst), "l"(src));
}
#define CP_COMMIT() asm volatile("cp.async.commit_group;\n" ::: "memory")
#define CP_WAIT1()  asm volatile("cp.async.wait_group 1;\n" ::: "memory")
#define CP_WAIT0()  asm volatile("cp.async.wait_group 0;\n" ::: "memory")

#define LDSM_X4(r0, r1, r2, r3, addr)                                        \
    asm volatile("ldmatrix.sync.aligned.m8n8.x4.shared.b16 {%0,%1,%2,%3}, [%4];" \
                 : "=r"(r0), "=r"(r1), "=r"(r2), "=r"(r3) : "r"(addr))

#define MMA_F16(d, a, b0, b1)                                                \
    asm volatile("mma.sync.aligned.m16n8k16.row.col.f32.f16.f16.f32 "        \
                 "{%0,%1,%2,%3}, {%4,%5,%6,%7}, {%8,%9}, {%0,%1,%2,%3};"     \
                 : "+f"((d)[0]), "+f"((d)[1]), "+f"((d)[2]), "+f"((d)[3])    \
                 : "r"((a)[0]), "r"((a)[1]), "r"((a)[2]), "r"((a)[3]),       \
                   "r"(b0), "r"(b1))

__device__ __forceinline__ uint32_t f2h2(float a, float b) {
    __half2 t = __floats2half2_rn(a, b);
    return *reinterpret_cast<uint32_t*>(&t);
}
__device__ __forceinline__ uint32_t ex2h2(float a, float b) {
    uint32_t x = f2h2(a, b), r;
    asm("ex2.approx.f16x2 %0, %1;" : "=r"(r) : "r"(x));
    return r;
}

// ---------------------------------------------------------------------------
// Conversion kernels
// ---------------------------------------------------------------------------
__global__ void convert_h_kernel(const float* __restrict__ in,
                                 __half* __restrict__ out, int n4)
{
    int i = blockIdx.x * blockDim.x + threadIdx.x;
    if (i >= n4) return;
    float4 x = ((const float4*)in)[i];
    ((uint2*)out)[i] = make_uint2(f2h2(x.x, x.y), f2h2(x.z, x.w));
}

// W[K,N] fp32 -> Wt[N,K] fp16 (tiled transpose)
__global__ void convert_w_kernel(const float* __restrict__ W,
                                 __half* __restrict__ out, int K, int N)
{
    __shared__ float t[32][33];
    int n0 = blockIdx.x * 32, k0 = blockIdx.y * 32;
    int tx = threadIdx.x, ty = threadIdx.y;  // 32 x 8
#pragma unroll
    for (int r = 0; r < 4; r++)
        t[ty + r * 8][tx] = W[(size_t)(k0 + ty + r * 8) * N + n0 + tx];
    __syncthreads();
#pragma unroll
    for (int r = 0; r < 4; r++) {
        float x = t[tx][ty + r * 8];
        out[(size_t)(n0 + ty + r * 8) * K + k0 + tx] = __float2half_rn(x);
    }
}

// ---------------------------------------------------------------------------
// mma.sync fp16 GEMM (single-A), XOR-swizzled smem, K-chunk 64,
// 3-stage cp.async pipeline with ONE __syncthreads per chunk:
//   wait1 -> sync -> load(c+2) -> commit -> compute(c)
// (load at iter c overwrites chunk c-1's buffer; every warp passed
//  compute(c-1) before this iteration's sync, so overwrite is safe.)
// CTA 128x128, 256 threads (8 warps of 64x32).
// mode 0: fp32 C out.  mode 1: QKV -> Q, K, V^T (fp16).
// ---------------------------------------------------------------------------
#define KC       64
#define NCH      (GK / KC)           // 32
#define TILE_B   (128 * 128)         // 16384
#define STAGE_B  (2 * TILE_B)        // 32768: A, B
#define GEMM_SMEM (3 * STAGE_B)      // 98304 -> 2 CTAs/SM

__global__ void __launch_bounds__(256, 2) mma_gemm_kernel(
    const __half* __restrict__ A, const __half* __restrict__ B,
    const float* __restrict__ bias, float* __restrict__ C, int N, int mode)
{
    extern __shared__ char smem[];
    const uint32_t sb = smem_u32(smem);
    const int tid = threadIdx.x;
    const int wid = tid >> 5, lane = tid & 31;
    const int n0 = blockIdx.x * 128, m0 = blockIdx.y * 128;
    const int wm = (wid & 1) * 64, wn = (wid >> 1) * 32;

    const uint32_t swx = (uint32_t)(lane & 7) << 4;
    const uint32_t arow = (uint32_t)(wm + (lane & 15)) * 128;
    const uint32_t acol = ((uint32_t)(lane >> 4) << 4);
    const uint32_t brow = (uint32_t)(wn + (lane & 7) + ((lane >> 4) << 3)) * 128;
    const uint32_t bcol = (((uint32_t)(lane >> 3) & 1) << 4);

    float acc[4][4][4];
#pragma unroll
    for (int mi = 0; mi < 4; mi++)
#pragma unroll
        for (int nj = 0; nj < 4; nj++)
#pragma unroll
            for (int d = 0; d < 4; d++) acc[mi][nj][d] = 0.f;

    auto load_chunk = [&](int c, int buf) {
        const int kk = c * KC;
        const uint32_t st = sb + buf * STAGE_B;
#pragma unroll
        for (int t = 0; t < 2; t++) {
            const int row0 = (t == 0) ? m0 : n0;
            const __half* src = (t == 0) ? A : B;
            const uint32_t dst = st + t * TILE_B;
#pragma unroll
            for (int i = 0; i < 4; i++) {
                int flat = tid + i * 256;
                int r = flat >> 3;
                int s = (flat & 7) * 16;
                uint32_t off = (uint32_t)r * 128 + (s ^ ((r & 7) << 4));
                cp_async16(dst + off,
                           (const char*)(src + (size_t)(row0 + r) * GK + kk) + s);
            }
        }
    };

    load_chunk(0, 0); CP_COMMIT();
    load_chunk(1, 1); CP_COMMIT();

    for (int c = 0; c < NCH; c++) {
        const int buf = c % 3;
        CP_WAIT1();          // own copies of chunk c done (committed c..c+1)
        __syncthreads();     // ALL threads' chunk-c copies done; also all
                             // warps finished compute(c-1) -> buf (c+2)%3 free
        if (c + 2 < NCH) load_chunk(c + 2, (c + 2) % 3);
        CP_COMMIT();

        const uint32_t sA = sb + buf * STAGE_B;
        const uint32_t sB = sA + TILE_B;
#pragma unroll
        for (int ks = 0; ks < 4; ks++) {
            const uint32_t kc = (uint32_t)ks * 32;
            uint32_t b2[2][4];
#pragma unroll
            for (int p = 0; p < 2; p++)
                LDSM_X4(b2[p][0], b2[p][1], b2[p][2], b2[p][3],
                        sB + brow + p * (16 * 128) + ((bcol + kc) ^ swx));
#pragma unroll
            for (int mi = 0; mi < 4; mi++) {
                uint32_t a4[4];
                LDSM_X4(a4[0], a4[1], a4[2], a4[3],
                        sA + arow + mi * (16 * 128) + ((acol + kc) ^ swx));
#pragma unroll
                for (int nj = 0; nj < 4; nj++) {
                    const int p = nj >> 1, e = (nj & 1) * 2;
                    MMA_F16(acc[mi][nj], a4, b2[p][e], b2[p][e + 1]);
                }
            }
        }
    }

    // ---- epilogue ----
    const int g = lane >> 2, tg = lane & 3;
#pragma unroll
    for (int mi = 0; mi < 4; mi++) {
#pragma unroll
        for (int half = 0; half < 2; half++) {
            const int m = m0 + wm + mi * 16 + g + half * 8;
            const int bb = m >> 11, s = m & (SEQ - 1);
#pragma unroll
            for (int nj = 0; nj < 4; nj++) {
                const int col = n0 + wn + nj * 8 + tg * 2;
                float v0 = acc[mi][nj][half * 2 + 0] + __ldg(&bias[col]);
                float v1 = acc[mi][nj][half * 2 + 1] + __ldg(&bias[col + 1]);
                if (mode == 0) {
                    *(float2*)(C + (size_t)m * N + col) = make_float2(v0, v1);
                } else {
                    const int part = col >> 11;
                    const int h = (col >> 7) & (NH - 1);
                    const int d0 = col & (HD - 1);
                    const size_t bh = (size_t)bb * NH + h;
                    if (part == 0) {
                        *(uint32_t*)(g_Q + (bh * SEQ + s) * HD + d0) = f2h2(v0, v1);
                    } else if (part == 1) {
                        *(uint32_t*)(g_K + (bh * SEQ + s) * HD + d0) = f2h2(v0, v1);
                    } else {
                        g_Vt[(bh * HD + d0)     * SEQ + s] = __float2half_rn(v0);
                        g_Vt[(bh * HD + d0 + 1) * SEQ + s] = __float2half_rn(v1);
                    }
                }
            }
        }
    }
}

// ---------------------------------------------------------------------------
// Tensor-core flash attention: causal + ALiBi in log2 domain, fp16 P via
// ex2.approx.f16x2, single-product PV, row sums via ones-MMA.
// Output written as single fp16 into g_A (proj input).
// ---------------------------------------------------------------------------
#define QSTR 272
#define VSTR 144
#define OFF_KS (128 * QSTR)
#define OFF_VS (OFF_KS + 64 * QSTR)
#define ATT_SMEM (OFF_VS + 128 * VSTR)
#define ONESH2 0x3C003C00u

__global__ void __launch_bounds__(256, 2) attn_mma_kernel()
{
    extern __shared__ char smc[];
    const uint32_t sb = smem_u32(smc);
    const int tid = threadIdx.x;
    const int wid = tid >> 5, lane = tid & 31;
    const int g = lane >> 2, tg = lane & 3;
    const int qt = blockIdx.x, h = blockIdx.y, b = blockIdx.z;
    const size_t bh = (size_t)b * NH + h;
    const int q0 = qt * 128;
    const int WR = wid * 16;

    const float scale2 = (1.f / 128.f) * LOG2E;
    const float slope2 = exp2f(-0.5f * (float)(h + 1)) * LOG2E;

    const uint32_t qbase = sb + (uint32_t)(WR + (lane & 15)) * QSTR + ((lane >> 4) << 4);
    const uint32_t kbase = sb + OFF_KS
        + (uint32_t)((lane & 7) + ((lane >> 4) << 3)) * QSTR + (((lane >> 3) & 1) << 4);
    const uint32_t vbase = sb + OFF_VS
        + (uint32_t)((lane & 7) + ((lane >> 4) << 3)) * VSTR + (((lane >> 3) & 1) << 4);

    {
        const __half* Q = g_Q + (bh * SEQ + q0) * HD;
#pragma unroll
        for (int i = 0; i < 8; i++) {
            int flat = tid + i * 256;
            int r = flat >> 4, cb = (flat & 15) * 16;
            cp_async16(sb + r * QSTR + cb, (const char*)(Q + (size_t)r * HD) + cb);
        }
        CP_COMMIT();
    }

    float oacc[16][4];
#pragma unroll
    for (int nf = 0; nf < 16; nf++)
#pragma unroll
        for (int d = 0; d < 4; d++) oacc[nf][d] = 0.f;
    float lacc[4] = {0.f, 0.f, 0.f, 0.f};
    float m_run[2] = {-1e30f, -1e30f};

    const int nkt = 2 * qt + 2;
    for (int kt = 0; kt < nkt; kt++) {
        const int s0 = kt * 64;
        __syncthreads();

        {
            const __half* K = g_K + (bh * SEQ + s0) * HD;
#pragma unroll
            for (int i = 0; i < 4; i++) {
                int flat = tid + i * 256;
                int r = flat >> 4, cb = (flat & 15) * 16;
                cp_async16(sb + OFF_KS + r * QSTR + cb,
                           (const char*)(K + (size_t)r * HD) + cb);
            }
            CP_COMMIT();
        }
        {
            const __half* V = g_Vt + bh * HD * SEQ + s0;
#pragma unroll
            for (int i = 0; i < 4; i++) {
                int flat = tid + i * 256;
                int r = flat >> 3, cb = (flat & 7) * 16;
                cp_async16(sb + OFF_VS + r * VSTR + cb,
                           (const char*)(V + (size_t)r * SEQ) + cb);
            }
            CP_COMMIT();
        }
        CP_WAIT1();
        __syncthreads();

        // ---- S = Q K^T ----
        float sacc[8][4];
#pragma unroll
        for (int nf = 0; nf < 8; nf++)
#pragma unroll
            for (int d = 0; d < 4; d++) sacc[nf][d] = 0.f;

#pragma unroll
        for (int ks = 0; ks < 8; ks++) {
            uint32_t ah[4];
            LDSM_X4(ah[0], ah[1], ah[2], ah[3], qbase + ks * 32);
#pragma unroll
            for (int j = 0; j < 4; j++) {
                uint32_t km[4];
                LDSM_X4(km[0], km[1], km[2], km[3],
                        kbase + j * (16 * QSTR) + ks * 32);
                MMA_F16(sacc[2 * j],     ah, km[0], km[1]);
                MMA_F16(sacc[2 * j + 1], ah, km[2], km[3]);
            }
        }

        // ---- bias + mask (log2 domain) ----
        const int row0 = q0 + WR + g;
        const int row1 = row0 + 8;
#pragma unroll
        for (int nf = 0; nf < 8; nf++) {
            const int cbase = s0 + nf * 8 + tg * 2;
#pragma unroll
            for (int e = 0; e < 2; e++) {
                const int col = cbase + e;
                float v0 = fmaf(sacc[nf][e], scale2, slope2 * (float)(col - row0));
                float v1 = fmaf(sacc[nf][2 + e], scale2, slope2 * (float)(col - row1));
                sacc[nf][e]     = (col > row0) ? -1e30f : v0;
                sacc[nf][2 + e] = (col > row1) ? -1e30f : v1;
            }
        }

        // ---- online max + rescale ----
        float m_new[2];
#pragma unroll
        for (int half = 0; half < 2; half++) {
            float mx = -1e30f;
#pragma unroll
            for (int nf = 0; nf < 8; nf++)
                mx = fmaxf(mx, fmaxf(sacc[nf][2 * half], sacc[nf][2 * half + 1]));
            mx = fmaxf(mx, __shfl_xor_sync(0xffffffffu, mx, 1));
            mx = fmaxf(mx, __shfl_xor_sync(0xffffffffu, mx, 2));
            m_new[half] = fmaxf(m_run[half], mx);
            float alpha = exp2f(m_run[half] - m_new[half]);
            m_run[half] = m_new[half];
#pragma unroll
            for (int nf = 0; nf < 16; nf++) {
                oacc[nf][2 * half] *= alpha;
                oacc[nf][2 * half + 1] *= alpha;
            }
            lacc[2 * half]     *= alpha;
            lacc[2 * half + 1] *= alpha;
        }

        // ---- P = exp2(S - m) as fp16x2 fragments ----
        uint32_t ph[8][2];
#pragma unroll
        for (int nf = 0; nf < 8; nf++) {
            ph[nf][0] = ex2h2(sacc[nf][0] - m_new[0], sacc[nf][1] - m_new[0]);
            ph[nf][1] = ex2h2(sacc[nf][2] - m_new[1], sacc[nf][3] - m_new[1]);
        }

        CP_WAIT0();
        __syncthreads();

        // ---- O += P V + row sums via ones-MMA ----
#pragma unroll
        for (int ks = 0; ks < 4; ks++) {
            uint32_t ap[4] = {ph[2 * ks][0], ph[2 * ks][1],
                              ph[2 * ks + 1][0], ph[2 * ks + 1][1]};
            MMA_F16(lacc, ap, ONESH2, ONESH2);
#pragma unroll
            for (int j = 0; j < 8; j++) {
                uint32_t vm[4];
                LDSM_X4(vm[0], vm[1], vm[2], vm[3],
                        vbase + j * (16 * VSTR) + ks * 32);
                MMA_F16(oacc[2 * j],     ap, vm[0], vm[1]);
                MMA_F16(oacc[2 * j + 1], ap, vm[2], vm[3]);
            }
        }
    }

    // ---- normalize + write single fp16 O into g_A ----
    const float inv0 = 1.f / lacc[0];
    const float inv1 = 1.f / lacc[2];
#pragma unroll
    for (int nf = 0; nf < 16; nf++) {
        const int d0 = nf * 8 + tg * 2;
        {
            const int m = b * SEQ + q0 + WR + g;
            *(uint32_t*)(g_A + (size_t)m * HID + h * HD + d0) =
                f2h2(oacc[nf][0] * inv0, oacc[nf][1] * inv0);
        }
        {
            const int m = b * SEQ + q0 + WR + g + 8;
            *(uint32_t*)(g_A + (size_t)m * HID + h * HD + d0) =
                f2h2(oacc[nf][2] * inv1, oacc[nf][3] * inv1);
        }
    }
}

// ---------------------------------------------------------------------------
extern "C" void kernel_launch(void* const* d_in, const int* in_sizes, int n_in,
                              void* d_out, int out_size)
{
    const float* hidden = (const float*)d_in[0];
    const float* w_qkv  = (const float*)d_in[1];
    const float* b_qkv  = (const float*)d_in[2];
    const float* w_proj = (const float*)d_in[3];
    const float* b_proj = (const float*)d_in[4];
    float* out = (float*)d_out;

    void *pA, *pWq, *pWp;
    cudaGetSymbolAddress(&pA, g_A);
    cudaGetSymbolAddress(&pWq, g_Wq);
    cudaGetSymbolAddress(&pWp, g_Wp);

    cudaFuncSetAttribute(mma_gemm_kernel,
                         cudaFuncAttributeMaxDynamicSharedMemorySize, GEMM_SMEM);
    cudaFuncSetAttribute(attn_mma_kernel,
                         cudaFuncAttributeMaxDynamicSharedMemorySize, ATT_SMEM);

    // weight conversion (transpose, single fp16)
    convert_w_kernel<<<dim3(3 * HID / 32, HID / 32), dim3(32, 8)>>>(
        w_qkv, (__half*)pWq, HID, 3 * HID);
    convert_w_kernel<<<dim3(HID / 32, HID / 32), dim3(32, 8)>>>(
        w_proj, (__half*)pWp, HID, HID);

    // hidden -> fp16 (QKV GEMM A input)
    {
        int n4 = MTOT * HID / 4;
        convert_h_kernel<<<(n4 + 255) / 256, 256>>>(hidden, (__half*)pA, n4);
    }

    // QKV GEMM -> Q, K, V^T (fp16)
    mma_gemm_kernel<<<dim3(3 * HID / 128, MTOT / 128), 256, GEMM_SMEM>>>(
        (const __half*)pA, (const __half*)pWq, b_qkv, nullptr, 3 * HID, 1);

    // tensor-core flash attention -> g_A (fp16)
    attn_mma_kernel<<<dim3(SEQ / 128, NH, BATCH), 256, ATT_SMEM>>>();

    // proj GEMM -> out
    mma_gemm_kernel<<<dim3(HID / 128, MTOT / 128), 256, GEMM_SMEM>>>(
        (const __half*)pA, (const __half*)pWp, b_proj, out, HID, 0);
}

// round 12
// speedup vs baseline: 1.5573x; 1.5573x over previous
#include <cuda_runtime.h>
#include <cuda_fp16.h>
#include <cstdint>

#define NH    16
#define HD    128
#define SEQ   2048
#define BATCH 2
#define HID   2048
#define MTOT  (BATCH * SEQ)   // 4096
#define GK    2048
#define LOG2E 1.4426950408889634f

// ---------------------------------------------------------------------------
// Scratch (__device__ globals — allocation-free)
// ---------------------------------------------------------------------------
__device__ __half g_Q [(size_t)BATCH * NH * SEQ * HD];  // Q [b,h,s,d]
__device__ __half g_K [(size_t)BATCH * NH * SEQ * HD];  // K [b,h,s,d]
__device__ __half g_Vt[(size_t)BATCH * NH * HD * SEQ];  // V [b,h,d,s]

__device__ __half g_A [(size_t)MTOT * HID];      // GEMM A (hidden / attn-out)
__device__ __half g_Wq[(size_t)3 * HID * HID];   // w_qkv^T fp16 [N,K]
__device__ __half g_Wp[(size_t)HID * HID];       // w_proj^T fp16 [N,K]

// ---------------------------------------------------------------------------
// helpers
// ---------------------------------------------------------------------------
__device__ __forceinline__ uint32_t smem_u32(const void* p) {
    uint32_t a;
    asm("{ .reg .u64 t; cvta.to.shared.u64 t, %1; cvt.u32.u64 %0, t; }"
        : "=r"(a) : "l"(p));
    return a;
}
__device__ __forceinline__ void cp_async16(uint32_t dst, const void* src) {
    asm volatile("cp.async.cg.shared.global [%0], [%1], 16;\n"
                 :: "r"(dst), "l"(src));
}
#define CP_COMMIT() asm volatile("cp.async.commit_group;\n" ::: "memory")
#define CP_WAIT1()  asm volatile("cp.async.wait_group 1;\n" ::: "memory")
#define CP_WAIT0()  asm volatile("cp.async.wait_group 0;\n" ::: "memory")

#define LDSM_X4(r0, r1, r2, r3, addr)                                        \
    asm volatile("ldmatrix.sync.aligned.m8n8.x4.shared.b16 {%0,%1,%2,%3}, [%4];" \
                 : "=r"(r0), "=r"(r1), "=r"(r2), "=r"(r3) : "r"(addr))

#define MMA_F16(d, a, b0, b1)                                                \
    asm volatile("mma.sync.aligned.m16n8k16.row.col.f32.f16.f16.f32 "        \
                 "{%0,%1,%2,%3}, {%4,%5,%6,%7}, {%8,%9}, {%0,%1,%2,%3};"     \
                 : "+f"((d)[0]), "+f"((d)[1]), "+f"((d)[2]), "+f"((d)[3])    \
                 : "r"((a)[0]), "r"((a)[1]), "r"((a)[2]), "r"((a)[3]),       \
                   "r"(b0), "r"(b1))

__device__ __forceinline__ uint32_t f2h2(float a, float b) {
    __half2 t = __floats2half2_rn(a, b);
    return *reinterpret_cast<uint32_t*>(&t);
}
__device__ __forceinline__ uint32_t ex2h2(float a, float b) {
    uint32_t x = f2h2(a, b), r;
    asm("ex2.approx.f16x2 %0, %1;" : "=r"(r) : "r"(x));
    return r;
}

// ---------------------------------------------------------------------------
// Conversion kernels
// ---------------------------------------------------------------------------
__global__ void convert_h_kernel(const float* __restrict__ in,
                                 __half* __restrict__ out, int n4)
{
    int i = blockIdx.x * blockDim.x + threadIdx.x;
    if (i >= n4) return;
    float4 x = ((const float4*)in)[i];
    ((uint2*)out)[i] = make_uint2(f2h2(x.x, x.y), f2h2(x.z, x.w));
}

// W[K,N] fp32 -> Wt[N,K] fp16 (tiled transpose)
__global__ void convert_w_kernel(const float* __restrict__ W,
                                 __half* __restrict__ out, int K, int N)
{
    __shared__ float t[32][33];
    int n0 = blockIdx.x * 32, k0 = blockIdx.y * 32;
    int tx = threadIdx.x, ty = threadIdx.y;  // 32 x 8
#pragma unroll
    for (int r = 0; r < 4; r++)
        t[ty + r * 8][tx] = W[(size_t)(k0 + ty + r * 8) * N + n0 + tx];
    __syncthreads();
#pragma unroll
    for (int r = 0; r < 4; r++) {
        float x = t[tx][ty + r * 8];
        out[(size_t)(n0 + ty + r * 8) * K + k0 + tx] = __float2half_rn(x);
    }
}

// ---------------------------------------------------------------------------
// mma.sync fp16 GEMM (single-A), XOR-swizzled smem, K-chunk 64.
// R10-proven 2-stage pipeline order (do NOT reorder):
//   sync -> load(c+1) -> commit -> wait1 -> sync -> compute(c)
// CTA 128x128, 256 threads (8 warps of 64x32).
// mode 0: fp32 C out.  mode 1: QKV -> Q, K, V^T (fp16).
// ---------------------------------------------------------------------------
#define KC       64
#define NCH      (GK / KC)           // 32
#define TILE_B   (128 * 128)         // 16384
#define STAGE_B  (2 * TILE_B)        // 32768: A, B
#define GEMM_SMEM (2 * STAGE_B)      // 65536 -> 2 CTAs/SM (reg-limited)

__global__ void __launch_bounds__(256, 2) mma_gemm_kernel(
    const __half* __restrict__ A, const __half* __restrict__ B,
    const float* __restrict__ bias, float* __restrict__ C, int N, int mode)
{
    extern __shared__ char smem[];
    const uint32_t sb = smem_u32(smem);
    const int tid = threadIdx.x;
    const int wid = tid >> 5, lane = tid & 31;
    const int n0 = blockIdx.x * 128, m0 = blockIdx.y * 128;
    const int wm = (wid & 1) * 64, wn = (wid >> 1) * 32;

    const uint32_t swx = (uint32_t)(lane & 7) << 4;
    const uint32_t arow = (uint32_t)(wm + (lane & 15)) * 128;
    const uint32_t acol = ((uint32_t)(lane >> 4) << 4);
    const uint32_t brow = (uint32_t)(wn + (lane & 7) + ((lane >> 4) << 3)) * 128;
    const uint32_t bcol = (((uint32_t)(lane >> 3) & 1) << 4);

    float acc[4][4][4];
#pragma unroll
    for (int mi = 0; mi < 4; mi++)
#pragma unroll
        for (int nj = 0; nj < 4; nj++)
#pragma unroll
            for (int d = 0; d < 4; d++) acc[mi][nj][d] = 0.f;

    auto load_chunk = [&](int c, int buf) {
        const int kk = c * KC;
        const uint32_t st = sb + buf * STAGE_B;
#pragma unroll
        for (int t = 0; t < 2; t++) {
            const int row0 = (t == 0) ? m0 : n0;
            const __half* src = (t == 0) ? A : B;
            const uint32_t dst = st + t * TILE_B;
#pragma unroll
            for (int i = 0; i < 4; i++) {
                int flat = tid + i * 256;
                int r = flat >> 3;
                int s = (flat & 7) * 16;
                uint32_t off = (uint32_t)r * 128 + (s ^ ((r & 7) << 4));
                cp_async16(dst + off,
                           (const char*)(src + (size_t)(row0 + r) * GK + kk) + s);
            }
        }
    };

    load_chunk(0, 0); CP_COMMIT();

    for (int c = 0; c < NCH; c++) {
        const int buf = c & 1;
        __syncthreads();                       // all warps done with buf^1
        if (c + 1 < NCH) load_chunk(c + 1, buf ^ 1);
        CP_COMMIT();
        CP_WAIT1();                            // own copies of chunk c done
        __syncthreads();                       // all threads' copies visible

        const uint32_t sA = sb + buf * STAGE_B;
        const uint32_t sB = sA + TILE_B;
#pragma unroll
        for (int ks = 0; ks < 4; ks++) {
            const uint32_t kc = (uint32_t)ks * 32;
            uint32_t b2[2][4];
#pragma unroll
            for (int p = 0; p < 2; p++)
                LDSM_X4(b2[p][0], b2[p][1], b2[p][2], b2[p][3],
                        sB + brow + p * (16 * 128) + ((bcol + kc) ^ swx));
#pragma unroll
            for (int mi = 0; mi < 4; mi++) {
                uint32_t a4[4];
                LDSM_X4(a4[0], a4[1], a4[2], a4[3],
                        sA + arow + mi * (16 * 128) + ((acol + kc) ^ swx));
#pragma unroll
                for (int nj = 0; nj < 4; nj++) {
                    const int p = nj >> 1, e = (nj & 1) * 2;
                    MMA_F16(acc[mi][nj], a4, b2[p][e], b2[p][e + 1]);
                }
            }
        }
    }

    // ---- epilogue ----
    const int g = lane >> 2, tg = lane & 3;
#pragma unroll
    for (int mi = 0; mi < 4; mi++) {
#pragma unroll
        for (int half = 0; half < 2; half++) {
            const int m = m0 + wm + mi * 16 + g + half * 8;
            const int bb = m >> 11, s = m & (SEQ - 1);
#pragma unroll
            for (int nj = 0; nj < 4; nj++) {
                const int col = n0 + wn + nj * 8 + tg * 2;
                float v0 = acc[mi][nj][half * 2 + 0] + __ldg(&bias[col]);
                float v1 = acc[mi][nj][half * 2 + 1] + __ldg(&bias[col + 1]);
                if (mode == 0) {
                    *(float2*)(C + (size_t)m * N + col) = make_float2(v0, v1);
                } else {
                    const int part = col >> 11;
                    const int h = (col >> 7) & (NH - 1);
                    const int d0 = col & (HD - 1);
                    const size_t bh = (size_t)bb * NH + h;
                    if (part == 0) {
                        *(uint32_t*)(g_Q + (bh * SEQ + s) * HD + d0) = f2h2(v0, v1);
                    } else if (part == 1) {
                        *(uint32_t*)(g_K + (bh * SEQ + s) * HD + d0) = f2h2(v0, v1);
                    } else {
                        g_Vt[(bh * HD + d0)     * SEQ + s] = __float2half_rn(v0);
                        g_Vt[(bh * HD + d0 + 1) * SEQ + s] = __float2half_rn(v1);
                    }
                }
            }
        }
    }
}

// ---------------------------------------------------------------------------
// Tensor-core flash attention: causal + ALiBi in log2 domain, fp16 P via
// ex2.approx.f16x2, single-product PV, row sums via ones-MMA.
// Output written as single fp16 into g_A (proj input).
// ---------------------------------------------------------------------------
#define QSTR 272
#define VSTR 144
#define OFF_KS (128 * QSTR)
#define OFF_VS (OFF_KS + 64 * QSTR)
#define ATT_SMEM (OFF_VS + 128 * VSTR)
#define ONESH2 0x3C003C00u

__global__ void __launch_bounds__(256, 2) attn_mma_kernel()
{
    extern __shared__ char smc[];
    const uint32_t sb = smem_u32(smc);
    const int tid = threadIdx.x;
    const int wid = tid >> 5, lane = tid & 31;
    const int g = lane >> 2, tg = lane & 3;
    const int qt = blockIdx.x, h = blockIdx.y, b = blockIdx.z;
    const size_t bh = (size_t)b * NH + h;
    const int q0 = qt * 128;
    const int WR = wid * 16;

    const float scale2 = (1.f / 128.f) * LOG2E;
    const float slope2 = exp2f(-0.5f * (float)(h + 1)) * LOG2E;

    const uint32_t qbase = sb + (uint32_t)(WR + (lane & 15)) * QSTR + ((lane >> 4) << 4);
    const uint32_t kbase = sb + OFF_KS
        + (uint32_t)((lane & 7) + ((lane >> 4) << 3)) * QSTR + (((lane >> 3) & 1) << 4);
    const uint32_t vbase = sb + OFF_VS
        + (uint32_t)((lane & 7) + ((lane >> 4) << 3)) * VSTR + (((lane >> 3) & 1) << 4);

    {
        const __half* Q = g_Q + (bh * SEQ + q0) * HD;
#pragma unroll
        for (int i = 0; i < 8; i++) {
            int flat = tid + i * 256;
            int r = flat >> 4, cb = (flat & 15) * 16;
            cp_async16(sb + r * QSTR + cb, (const char*)(Q + (size_t)r * HD) + cb);
        }
        CP_COMMIT();
    }

    float oacc[16][4];
#pragma unroll
    for (int nf = 0; nf < 16; nf++)
#pragma unroll
        for (int d = 0; d < 4; d++) oacc[nf][d] = 0.f;
    float lacc[4] = {0.f, 0.f, 0.f, 0.f};
    float m_run[2] = {-1e30f, -1e30f};

    const int nkt = 2 * qt + 2;
    for (int kt = 0; kt < nkt; kt++) {
        const int s0 = kt * 64;
        __syncthreads();

        {
            const __half* K = g_K + (bh * SEQ + s0) * HD;
#pragma unroll
            for (int i = 0; i < 4; i++) {
                int flat = tid + i * 256;
                int r = flat >> 4, cb = (flat & 15) * 16;
                cp_async16(sb + OFF_KS + r * QSTR + cb,
                           (const char*)(K + (size_t)r * HD) + cb);
            }
            CP_COMMIT();
        }
        {
            const __half* V = g_Vt + bh * HD * SEQ + s0;
#pragma unroll
            for (int i = 0; i < 4; i++) {
                int flat = tid + i * 256;
                int r = flat >> 3, cb = (flat & 7) * 16;
                cp_async16(sb + OFF_VS + r * VSTR + cb,
                           (const char*)(V + (size_t)r * SEQ) + cb);
            }
            CP_COMMIT();
        }
        CP_WAIT1();
        __syncthreads();

        // ---- S = Q K^T ----
        float sacc[8][4];
#pragma unroll
        for (int nf = 0; nf < 8; nf++)
#pragma unroll
            for (int d = 0; d < 4; d++) sacc[nf][d] = 0.f;

#pragma unroll
        for (int ks = 0; ks < 8; ks++) {
            uint32_t ah[4];
            LDSM_X4(ah[0], ah[1], ah[2], ah[3], qbase + ks * 32);
#pragma unroll
            for (int j = 0; j < 4; j++) {
                uint32_t km[4];
                LDSM_X4(km[0], km[1], km[2], km[3],
                        kbase + j * (16 * QSTR) + ks * 32);
                MMA_F16(sacc[2 * j],     ah, km[0], km[1]);
                MMA_F16(sacc[2 * j + 1], ah, km[2], km[3]);
            }
        }

        // ---- bias + mask (log2 domain) ----
        const int row0 = q0 + WR + g;
        const int row1 = row0 + 8;
#pragma unroll
        for (int nf = 0; nf < 8; nf++) {
            const int cbase = s0 + nf * 8 + tg * 2;
#pragma unroll
            for (int e = 0; e < 2; e++) {
                const int col = cbase + e;
                float v0 = fmaf(sacc[nf][e], scale2, slope2 * (float)(col - row0));
                float v1 = fmaf(sacc[nf][2 + e], scale2, slope2 * (float)(col - row1));
                sacc[nf][e]     = (col > row0) ? -1e30f : v0;
                sacc[nf][2 + e] = (col > row1) ? -1e30f : v1;
            }
        }

        // ---- online max + rescale ----
        float m_new[2];
#pragma unroll
        for (int half = 0; half < 2; half++) {
            float mx = -1e30f;
#pragma unroll
            for (int nf = 0; nf < 8; nf++)
                mx = fmaxf(mx, fmaxf(sacc[nf][2 * half], sacc[nf][2 * half + 1]));
            mx = fmaxf(mx, __shfl_xor_sync(0xffffffffu, mx, 1));
            mx = fmaxf(mx, __shfl_xor_sync(0xffffffffu, mx, 2));
            m_new[half] = fmaxf(m_run[half], mx);
            float alpha = exp2f(m_run[half] - m_new[half]);
            m_run[half] = m_new[half];
#pragma unroll
            for (int nf = 0; nf < 16; nf++) {
                oacc[nf][2 * half] *= alpha;
                oacc[nf][2 * half + 1] *= alpha;
            }
            lacc[2 * half]     *= alpha;
            lacc[2 * half + 1] *= alpha;
        }

        // ---- P = exp2(S - m) as fp16x2 fragments ----
        uint32_t ph[8][2];
#pragma unroll
        for (int nf = 0; nf < 8; nf++) {
            ph[nf][0] = ex2h2(sacc[nf][0] - m_new[0], sacc[nf][1] - m_new[0]);
            ph[nf][1] = ex2h2(sacc[nf][2] - m_new[1], sacc[nf][3] - m_new[1]);
        }

        CP_WAIT0();
        __syncthreads();

        // ---- O += P V + row sums via ones-MMA ----
#pragma unroll
        for (int ks = 0; ks < 4; ks++) {
            uint32_t ap[4] = {ph[2 * ks][0], ph[2 * ks][1],
                              ph[2 * ks + 1][0], ph[2 * ks + 1][1]};
            MMA_F16(lacc, ap, ONESH2, ONESH2);
#pragma unroll
            for (int j = 0; j < 8; j++) {
                uint32_t vm[4];
                LDSM_X4(vm[0], vm[1], vm[2], vm[3],
                        vbase + j * (16 * VSTR) + ks * 32);
                MMA_F16(oacc[2 * j],     ap, vm[0], vm[1]);
                MMA_F16(oacc[2 * j + 1], ap, vm[2], vm[3]);
            }
        }
    }

    // ---- normalize + write single fp16 O into g_A ----
    const float inv0 = 1.f / lacc[0];
    const float inv1 = 1.f / lacc[2];
#pragma unroll
    for (int nf = 0; nf < 16; nf++) {
        const int d0 = nf * 8 + tg * 2;
        {
            const int m = b * SEQ + q0 + WR + g;
            *(uint32_t*)(g_A + (size_t)m * HID + h * HD + d0) =
                f2h2(oacc[nf][0] * inv0, oacc[nf][1] * inv0);
        }
        {
            const int m = b * SEQ + q0 + WR + g + 8;
            *(uint32_t*)(g_A + (size_t)m * HID + h * HD + d0) =
                f2h2(oacc[nf][2] * inv1, oacc[nf][3] * inv1);
        }
    }
}

// ---------------------------------------------------------------------------
extern "C" void kernel_launch(void* const* d_in, const int* in_sizes, int n_in,
                              void* d_out, int out_size)
{
    const float* hidden = (const float*)d_in[0];
    const float* w_qkv  = (const float*)d_in[1];
    const float* b_qkv  = (const float*)d_in[2];
    const float* w_proj = (const float*)d_in[3];
    const float* b_proj = (const float*)d_in[4];
    float* out = (float*)d_out;

    void *pA, *pWq, *pWp;
    cudaGetSymbolAddress(&pA, g_A);
    cudaGetSymbolAddress(&pWq, g_Wq);
    cudaGetSymbolAddress(&pWp, g_Wp);

    cudaFuncSetAttribute(mma_gemm_kernel,
                         cudaFuncAttributeMaxDynamicSharedMemorySize, GEMM_SMEM);
    cudaFuncSetAttribute(attn_mma_kernel,
                         cudaFuncAttributeMaxDynamicSharedMemorySize, ATT_SMEM);

    // weight conversion (transpose, single fp16)
    convert_w_kernel<<<dim3(3 * HID / 32, HID / 32), dim3(32, 8)>>>(
        w_qkv, (__half*)pWq, HID, 3 * HID);
    convert_w_kernel<<<dim3(HID / 32, HID / 32), dim3(32, 8)>>>(
        w_proj, (__half*)pWp, HID, HID);

    // hidden -> fp16 (QKV GEMM A input)
    {
        int n4 = MTOT * HID / 4;
        convert_h_kernel<<<(n4 + 255) / 256, 256>>>(hidden, (__half*)pA, n4);
    }

    // QKV GEMM -> Q, K, V^T (fp16)
    mma_gemm_kernel<<<dim3(3 * HID / 128, MTOT / 128), 256, GEMM_SMEM>>>(
        (const __half*)pA, (const __half*)pWq, b_qkv, nullptr, 3 * HID, 1);

    // tensor-core flash attention -> g_A (fp16)
    attn_mma_kernel<<<dim3(SEQ / 128, NH, BATCH), 256, ATT_SMEM>>>();

    // proj GEMM -> out
    mma_gemm_kernel<<<dim3(HID / 128, MTOT / 128), 256, GEMM_SMEM>>>(
        (const __half*)pA, (const __half*)pWp, b_proj, out, HID, 0);
}

// round 13
// speedup vs baseline: 1.6877x; 1.0837x over previous
#include <cuda_runtime.h>
#include <cuda_fp16.h>
#include <cstdint>

#define NH    16
#define HD    128
#define SEQ   2048
#define BATCH 2
#define HID   2048
#define MTOT  (BATCH * SEQ)   // 4096
#define GK    2048
#define LOG2E 1.4426950408889634f

// ---------------------------------------------------------------------------
// Scratch (__device__ globals — allocation-free)
// ---------------------------------------------------------------------------
__device__ __half g_Q [(size_t)BATCH * NH * SEQ * HD];  // Q [b,h,s,d]
__device__ __half g_K [(size_t)BATCH * NH * SEQ * HD];  // K [b,h,s,d]
__device__ __half g_Vt[(size_t)BATCH * NH * HD * SEQ];  // V [b,h,d,s]

__device__ __half g_A [(size_t)MTOT * HID];      // GEMM A (hidden / attn-out)
__device__ __half g_Wq[(size_t)3 * HID * HID];   // w_qkv^T fp16 [N,K]
__device__ __half g_Wp[(size_t)HID * HID];       // w_proj^T fp16 [N,K]

// ---------------------------------------------------------------------------
// helpers
// ---------------------------------------------------------------------------
__device__ __forceinline__ uint32_t smem_u32(const void* p) {
    uint32_t a;
    asm("{ .reg .u64 t; cvta.to.shared.u64 t, %1; cvt.u32.u64 %0, t; }"
        : "=r"(a) : "l"(p));
    return a;
}
__device__ __forceinline__ void cp_async16(uint32_t dst, const void* src) {
    asm volatile("cp.async.cg.shared.global [%0], [%1], 16;\n"
                 :: "r"(dst), "l"(src));
}
#define CP_COMMIT() asm volatile("cp.async.commit_group;\n" ::: "memory")
#define CP_WAIT1()  asm volatile("cp.async.wait_group 1;\n" ::: "memory")
#define CP_WAIT0()  asm volatile("cp.async.wait_group 0;\n" ::: "memory")

#define LDSM_X4(r0, r1, r2, r3, addr)                                        \
    asm volatile("ldmatrix.sync.aligned.m8n8.x4.shared.b16 {%0,%1,%2,%3}, [%4];" \
                 : "=r"(r0), "=r"(r1), "=r"(r2), "=r"(r3) : "r"(addr))

#define MMA_F16(d, a, b0, b1)                                                \
    asm volatile("mma.sync.aligned.m16n8k16.row.col.f32.f16.f16.f32 "        \
                 "{%0,%1,%2,%3}, {%4,%5,%6,%7}, {%8,%9}, {%0,%1,%2,%3};"     \
                 : "+f"((d)[0]), "+f"((d)[1]), "+f"((d)[2]), "+f"((d)[3])    \
                 : "r"((a)[0]), "r"((a)[1]), "r"((a)[2]), "r"((a)[3]),       \
                   "r"(b0), "r"(b1))

__device__ __forceinline__ uint32_t f2h2(float a, float b) {
    __half2 t = __floats2half2_rn(a, b);
    return *reinterpret_cast<uint32_t*>(&t);
}
__device__ __forceinline__ uint32_t ex2h2(float a, float b) {
    uint32_t x = f2h2(a, b), r;
    asm("ex2.approx.f16x2 %0, %1;" : "=r"(r) : "r"(x));
    return r;
}

// ---------------------------------------------------------------------------
// Conversion kernels
// ---------------------------------------------------------------------------
__global__ void convert_h_kernel(const float* __restrict__ in,
                                 __half* __restrict__ out, int n4)
{
    int i = blockIdx.x * blockDim.x + threadIdx.x;
    if (i >= n4) return;
    float4 x = ((const float4*)in)[i];
    ((uint2*)out)[i] = make_uint2(f2h2(x.x, x.y), f2h2(x.z, x.w));
}

// W[K,N] fp32 -> Wt[N,K] fp16 (tiled transpose)
__global__ void convert_w_kernel(const float* __restrict__ W,
                                 __half* __restrict__ out, int K, int N)
{
    __shared__ float t[32][33];
    int n0 = blockIdx.x * 32, k0 = blockIdx.y * 32;
    int tx = threadIdx.x, ty = threadIdx.y;  // 32 x 8
#pragma unroll
    for (int r = 0; r < 4; r++)
        t[ty + r * 8][tx] = W[(size_t)(k0 + ty + r * 8) * N + n0 + tx];
    __syncthreads();
#pragma unroll
    for (int r = 0; r < 4; r++) {
        float x = t[tx][ty + r * 8];
        out[(size_t)(n0 + ty + r * 8) * K + k0 + tx] = __float2half_rn(x);
    }
}

// ---------------------------------------------------------------------------
// mma.sync fp16 GEMM (single-A), XOR-swizzled smem, K-chunk 64.
// R10-proven 2-stage pipeline order (do NOT reorder):
//   sync -> load(c+1) -> commit -> wait1 -> sync -> compute(c)
// CTA 128x128, 256 threads (8 warps of 64x32).
// mode 0: fp32 C out.  mode 1: QKV -> Q, K, V^T (fp16).
// ---------------------------------------------------------------------------
#define KC       64
#define NCH      (GK / KC)           // 32
#define TILE_B   (128 * 128)         // 16384
#define STAGE_B  (2 * TILE_B)        // 32768: A, B
#define GEMM_SMEM (2 * STAGE_B)      // 65536

__global__ void __launch_bounds__(256, 2) mma_gemm_kernel(
    const __half* __restrict__ A, const __half* __restrict__ B,
    const float* __restrict__ bias, float* __restrict__ C, int N, int mode)
{
    extern __shared__ char smem[];
    const uint32_t sb = smem_u32(smem);
    const int tid = threadIdx.x;
    const int wid = tid >> 5, lane = tid & 31;
    const int n0 = blockIdx.x * 128, m0 = blockIdx.y * 128;
    const int wm = (wid & 1) * 64, wn = (wid >> 1) * 32;

    const uint32_t swx = (uint32_t)(lane & 7) << 4;
    const uint32_t arow = (uint32_t)(wm + (lane & 15)) * 128;
    const uint32_t acol = ((uint32_t)(lane >> 4) << 4);
    const uint32_t brow = (uint32_t)(wn + (lane & 7) + ((lane >> 4) << 3)) * 128;
    const uint32_t bcol = (((uint32_t)(lane >> 3) & 1) << 4);

    float acc[4][4][4];
#pragma unroll
    for (int mi = 0; mi < 4; mi++)
#pragma unroll
        for (int nj = 0; nj < 4; nj++)
#pragma unroll
            for (int d = 0; d < 4; d++) acc[mi][nj][d] = 0.f;

    auto load_chunk = [&](int c, int buf) {
        const int kk = c * KC;
        const uint32_t st = sb + buf * STAGE_B;
#pragma unroll
        for (int t = 0; t < 2; t++) {
            const int row0 = (t == 0) ? m0 : n0;
            const __half* src = (t == 0) ? A : B;
            const uint32_t dst = st + t * TILE_B;
#pragma unroll
            for (int i = 0; i < 4; i++) {
                int flat = tid + i * 256;
                int r = flat >> 3;
                int s = (flat & 7) * 16;
                uint32_t off = (uint32_t)r * 128 + (s ^ ((r & 7) << 4));
                cp_async16(dst + off,
                           (const char*)(src + (size_t)(row0 + r) * GK + kk) + s);
            }
        }
    };

    load_chunk(0, 0); CP_COMMIT();

    for (int c = 0; c < NCH; c++) {
        const int buf = c & 1;
        __syncthreads();                       // all warps done with buf^1
        if (c + 1 < NCH) load_chunk(c + 1, buf ^ 1);
        CP_COMMIT();
        CP_WAIT1();                            // own copies of chunk c done
        __syncthreads();                       // all threads' copies visible

        const uint32_t sA = sb + buf * STAGE_B;
        const uint32_t sB = sA + TILE_B;
#pragma unroll
        for (int ks = 0; ks < 4; ks++) {
            const uint32_t kc = (uint32_t)ks * 32;
            uint32_t b2[2][4];
#pragma unroll
            for (int p = 0; p < 2; p++)
                LDSM_X4(b2[p][0], b2[p][1], b2[p][2], b2[p][3],
                        sB + brow + p * (16 * 128) + ((bcol + kc) ^ swx));
#pragma unroll
            for (int mi = 0; mi < 4; mi++) {
                uint32_t a4[4];
                LDSM_X4(a4[0], a4[1], a4[2], a4[3],
                        sA + arow + mi * (16 * 128) + ((acol + kc) ^ swx));
#pragma unroll
                for (int nj = 0; nj < 4; nj++) {
                    const int p = nj >> 1, e = (nj & 1) * 2;
                    MMA_F16(acc[mi][nj], a4, b2[p][e], b2[p][e + 1]);
                }
            }
        }
    }

    // ---- epilogue ----
    const int g = lane >> 2, tg = lane & 3;
#pragma unroll
    for (int mi = 0; mi < 4; mi++) {
#pragma unroll
        for (int half = 0; half < 2; half++) {
            const int m = m0 + wm + mi * 16 + g + half * 8;
            const int bb = m >> 11, s = m & (SEQ - 1);
#pragma unroll
            for (int nj = 0; nj < 4; nj++) {
                const int col = n0 + wn + nj * 8 + tg * 2;
                float v0 = acc[mi][nj][half * 2 + 0] + __ldg(&bias[col]);
                float v1 = acc[mi][nj][half * 2 + 1] + __ldg(&bias[col + 1]);
                if (mode == 0) {
                    *(float2*)(C + (size_t)m * N + col) = make_float2(v0, v1);
                } else {
                    const int part = col >> 11;
                    const int h = (col >> 7) & (NH - 1);
                    const int d0 = col & (HD - 1);
                    const size_t bh = (size_t)bb * NH + h;
                    if (part == 0) {
                        *(uint32_t*)(g_Q + (bh * SEQ + s) * HD + d0) = f2h2(v0, v1);
                    } else if (part == 1) {
                        *(uint32_t*)(g_K + (bh * SEQ + s) * HD + d0) = f2h2(v0, v1);
                    } else {
                        g_Vt[(bh * HD + d0)     * SEQ + s] = __float2half_rn(v0);
                        g_Vt[(bh * HD + d0 + 1) * SEQ + s] = __float2half_rn(v1);
                    }
                }
            }
        }
    }
}

// ---------------------------------------------------------------------------
// Tensor-core flash attention: causal + ALiBi in log2 domain, fp16 P via
// ex2.approx.f16x2, single-product PV, row sums via ones-MMA.
// Balanced persistent mapping: 256 CTAs, CTA j handles work items j and
// 511-j (items sorted qt-descending) -> every CTA does exactly 34 k-tiles,
// single wave (256 <= 296 slots).
// Output written as single fp16 into g_A (proj input).
// ---------------------------------------------------------------------------
#define QSTR 272
#define VSTR 144
#define OFF_KS (128 * QSTR)
#define OFF_VS (OFF_KS + 64 * QSTR)
#define ATT_SMEM (OFF_VS + 128 * VSTR)
#define ONESH2 0x3C003C00u
#define NITEMS (16 * NH * BATCH)     // 512

__global__ void __launch_bounds__(256, 2) attn_mma_kernel()
{
    extern __shared__ char smc[];
    const uint32_t sb = smem_u32(smc);
    const int tid = threadIdx.x;
    const int wid = tid >> 5, lane = tid & 31;
    const int g = lane >> 2, tg = lane & 3;
    const int WR = wid * 16;

    const uint32_t qbase = sb + (uint32_t)(WR + (lane & 15)) * QSTR + ((lane >> 4) << 4);
    const uint32_t kbase = sb + OFF_KS
        + (uint32_t)((lane & 7) + ((lane >> 4) << 3)) * QSTR + (((lane >> 3) & 1) << 4);
    const uint32_t vbase = sb + OFF_VS
        + (uint32_t)((lane & 7) + ((lane >> 4) << 3)) * VSTR + (((lane >> 3) & 1) << 4);

#pragma unroll 1
    for (int sel = 0; sel < 2; sel++) {
        const int it = sel ? (NITEMS - 1 - (int)blockIdx.x) : (int)blockIdx.x;
        // items sorted by qt descending: it 0..31 -> qt=15 (all h,b), etc.
        const int qt = 15 - (it >> 5);
        const int h  = (it & 31) >> 1;
        const int b  = it & 1;
        const size_t bh = (size_t)b * NH + h;
        const int q0 = qt * 128;

        const float scale2 = (1.f / 128.f) * LOG2E;
        const float slope2 = exp2f(-0.5f * (float)(h + 1)) * LOG2E;

        // ---- stage Q ----
        {
            const __half* Q = g_Q + (bh * SEQ + q0) * HD;
#pragma unroll
            for (int i = 0; i < 8; i++) {
                int flat = tid + i * 256;
                int r = flat >> 4, cb = (flat & 15) * 16;
                cp_async16(sb + r * QSTR + cb,
                           (const char*)(Q + (size_t)r * HD) + cb);
            }
            CP_COMMIT();
        }

        float oacc[16][4];
#pragma unroll
        for (int nf = 0; nf < 16; nf++)
#pragma unroll
            for (int d = 0; d < 4; d++) oacc[nf][d] = 0.f;
        float lacc[4] = {0.f, 0.f, 0.f, 0.f};
        float m_run[2] = {-1e30f, -1e30f};

        const int nkt = 2 * qt + 2;
        for (int kt = 0; kt < nkt; kt++) {
            const int s0 = kt * 64;
            __syncthreads();

            {
                const __half* K = g_K + (bh * SEQ + s0) * HD;
#pragma unroll
                for (int i = 0; i < 4; i++) {
                    int flat = tid + i * 256;
                    int r = flat >> 4, cb = (flat & 15) * 16;
                    cp_async16(sb + OFF_KS + r * QSTR + cb,
                               (const char*)(K + (size_t)r * HD) + cb);
                }
                CP_COMMIT();
            }
            {
                const __half* V = g_Vt + bh * HD * SEQ + s0;
#pragma unroll
                for (int i = 0; i < 4; i++) {
                    int flat = tid + i * 256;
                    int r = flat >> 3, cb = (flat & 7) * 16;
                    cp_async16(sb + OFF_VS + r * VSTR + cb,
                               (const char*)(V + (size_t)r * SEQ) + cb);
                }
                CP_COMMIT();
            }
            CP_WAIT1();
            __syncthreads();

            // ---- S = Q K^T ----
            float sacc[8][4];
#pragma unroll
            for (int nf = 0; nf < 8; nf++)
#pragma unroll
                for (int d = 0; d < 4; d++) sacc[nf][d] = 0.f;

#pragma unroll
            for (int ks = 0; ks < 8; ks++) {
                uint32_t ah[4];
                LDSM_X4(ah[0], ah[1], ah[2], ah[3], qbase + ks * 32);
#pragma unroll
                for (int j = 0; j < 4; j++) {
                    uint32_t km[4];
                    LDSM_X4(km[0], km[1], km[2], km[3],
                            kbase + j * (16 * QSTR) + ks * 32);
                    MMA_F16(sacc[2 * j],     ah, km[0], km[1]);
                    MMA_F16(sacc[2 * j + 1], ah, km[2], km[3]);
                }
            }

            // ---- bias + mask (log2 domain) ----
            const int row0 = q0 + WR + g;
            const int row1 = row0 + 8;
#pragma unroll
            for (int nf = 0; nf < 8; nf++) {
                const int cbase = s0 + nf * 8 + tg * 2;
#pragma unroll
                for (int e = 0; e < 2; e++) {
                    const int col = cbase + e;
                    float v0 = fmaf(sacc[nf][e], scale2, slope2 * (float)(col - row0));
                    float v1 = fmaf(sacc[nf][2 + e], scale2, slope2 * (float)(col - row1));
                    sacc[nf][e]     = (col > row0) ? -1e30f : v0;
                    sacc[nf][2 + e] = (col > row1) ? -1e30f : v1;
                }
            }

            // ---- online max + rescale ----
            float m_new[2];
#pragma unroll
            for (int half = 0; half < 2; half++) {
                float mx = -1e30f;
#pragma unroll
                for (int nf = 0; nf < 8; nf++)
                    mx = fmaxf(mx, fmaxf(sacc[nf][2 * half], sacc[nf][2 * half + 1]));
                mx = fmaxf(mx, __shfl_xor_sync(0xffffffffu, mx, 1));
                mx = fmaxf(mx, __shfl_xor_sync(0xffffffffu, mx, 2));
                m_new[half] = fmaxf(m_run[half], mx);
                float alpha = exp2f(m_run[half] - m_new[half]);
                m_run[half] = m_new[half];
#pragma unroll
                for (int nf = 0; nf < 16; nf++) {
                    oacc[nf][2 * half] *= alpha;
                    oacc[nf][2 * half + 1] *= alpha;
                }
                lacc[2 * half]     *= alpha;
                lacc[2 * half + 1] *= alpha;
            }

            // ---- P = exp2(S - m) as fp16x2 fragments ----
            uint32_t ph[8][2];
#pragma unroll
            for (int nf = 0; nf < 8; nf++) {
                ph[nf][0] = ex2h2(sacc[nf][0] - m_new[0], sacc[nf][1] - m_new[0]);
                ph[nf][1] = ex2h2(sacc[nf][2] - m_new[1], sacc[nf][3] - m_new[1]);
            }

            CP_WAIT0();
            __syncthreads();

            // ---- O += P V + row sums via ones-MMA ----
#pragma unroll
            for (int ks = 0; ks < 4; ks++) {
                uint32_t ap[4] = {ph[2 * ks][0], ph[2 * ks][1],
                                  ph[2 * ks + 1][0], ph[2 * ks + 1][1]};
                MMA_F16(lacc, ap, ONESH2, ONESH2);
#pragma unroll
                for (int j = 0; j < 8; j++) {
                    uint32_t vm[4];
                    LDSM_X4(vm[0], vm[1], vm[2], vm[3],
                            vbase + j * (16 * VSTR) + ks * 32);
                    MMA_F16(oacc[2 * j],     ap, vm[0], vm[1]);
                    MMA_F16(oacc[2 * j + 1], ap, vm[2], vm[3]);
                }
            }
        }

        // ---- normalize + write single fp16 O into g_A ----
        const float inv0 = 1.f / lacc[0];
        const float inv1 = 1.f / lacc[2];
#pragma unroll
        for (int nf = 0; nf < 16; nf++) {
            const int d0 = nf * 8 + tg * 2;
            {
                const int m = b * SEQ + q0 + WR + g;
                *(uint32_t*)(g_A + (size_t)m * HID + h * HD + d0) =
                    f2h2(oacc[nf][0] * inv0, oacc[nf][1] * inv0);
            }
            {
                const int m = b * SEQ + q0 + WR + g + 8;
                *(uint32_t*)(g_A + (size_t)m * HID + h * HD + d0) =
                    f2h2(oacc[nf][2] * inv1, oacc[nf][3] * inv1);
            }
        }
        __syncthreads();   // all warps done with smem before next item's Q load
    }
}

// ---------------------------------------------------------------------------
extern "C" void kernel_launch(void* const* d_in, const int* in_sizes, int n_in,
                              void* d_out, int out_size)
{
    const float* hidden = (const float*)d_in[0];
    const float* w_qkv  = (const float*)d_in[1];
    const float* b_qkv  = (const float*)d_in[2];
    const float* w_proj = (const float*)d_in[3];
    const float* b_proj = (const float*)d_in[4];
    float* out = (float*)d_out;

    void *pA, *pWq, *pWp;
    cudaGetSymbolAddress(&pA, g_A);
    cudaGetSymbolAddress(&pWq, g_Wq);
    cudaGetSymbolAddress(&pWp, g_Wp);

    cudaFuncSetAttribute(mma_gemm_kernel,
                         cudaFuncAttributeMaxDynamicSharedMemorySize, GEMM_SMEM);
    cudaFuncSetAttribute(attn_mma_kernel,
                         cudaFuncAttributeMaxDynamicSharedMemorySize, ATT_SMEM);

    // weight conversion (transpose, single fp16)
    convert_w_kernel<<<dim3(3 * HID / 32, HID / 32), dim3(32, 8)>>>(
        w_qkv, (__half*)pWq, HID, 3 * HID);
    convert_w_kernel<<<dim3(HID / 32, HID / 32), dim3(32, 8)>>>(
        w_proj, (__half*)pWp, HID, HID);

    // hidden -> fp16 (QKV GEMM A input)
    {
        int n4 = MTOT * HID / 4;
        convert_h_kernel<<<(n4 + 255) / 256, 256>>>(hidden, (__half*)pA, n4);
    }

    // QKV GEMM -> Q, K, V^T (fp16)
    mma_gemm_kernel<<<dim3(3 * HID / 128, MTOT / 128), 256, GEMM_SMEM>>>(
        (const __half*)pA, (const __half*)pWq, b_qkv, nullptr, 3 * HID, 1);

    // balanced tensor-core flash attention -> g_A (fp16)
    attn_mma_kernel<<<NITEMS / 2, 256, ATT_SMEM>>>();

    // proj GEMM -> out
    mma_gemm_kernel<<<dim3(HID / 128, MTOT / 128), 256, GEMM_SMEM>>>(
        (const __half*)pA, (const __half*)pWp, b_proj, out, HID, 0);
}

// round 14
// speedup vs baseline: 1.7002x; 1.0074x over previous
#include <cuda_runtime.h>
#include <cuda_fp16.h>
#include <cstdint>

#define NH    16
#define HD    128
#define SEQ   2048
#define BATCH 2
#define HID   2048
#define MTOT  (BATCH * SEQ)   // 4096
#define GK    2048
#define LOG2E 1.4426950408889634f

// ---------------------------------------------------------------------------
// Scratch (__device__ globals — allocation-free)
// ---------------------------------------------------------------------------
__device__ __half g_Q[(size_t)BATCH * NH * SEQ * HD];  // Q [b,h,s,d]
__device__ __half g_K[(size_t)BATCH * NH * SEQ * HD];  // K [b,h,s,d]
__device__ __half g_V[(size_t)BATCH * NH * SEQ * HD];  // V [b,h,s,d] (row-major!)

__device__ __half g_A [(size_t)MTOT * HID];      // GEMM A (hidden / attn-out)
__device__ __half g_Wq[(size_t)3 * HID * HID];   // w_qkv^T fp16 [N,K]
__device__ __half g_Wp[(size_t)HID * HID];       // w_proj^T fp16 [N,K]

// ---------------------------------------------------------------------------
// helpers
// ---------------------------------------------------------------------------
__device__ __forceinline__ uint32_t smem_u32(const void* p) {
    uint32_t a;
    asm("{ .reg .u64 t; cvta.to.shared.u64 t, %1; cvt.u32.u64 %0, t; }"
        : "=r"(a) : "l"(p));
    return a;
}
__device__ __forceinline__ void cp_async16(uint32_t dst, const void* src) {
    asm volatile("cp.async.cg.shared.global [%0], [%1], 16;\n"
                 :: "r"(dst), "l"(src));
}
#define CP_COMMIT() asm volatile("cp.async.commit_group;\n" ::: "memory")
#define CP_WAIT1()  asm volatile("cp.async.wait_group 1;\n" ::: "memory")
#define CP_WAIT0()  asm volatile("cp.async.wait_group 0;\n" ::: "memory")

#define LDSM_X4(r0, r1, r2, r3, addr)                                        \
    asm volatile("ldmatrix.sync.aligned.m8n8.x4.shared.b16 {%0,%1,%2,%3}, [%4];" \
                 : "=r"(r0), "=r"(r1), "=r"(r2), "=r"(r3) : "r"(addr))

#define LDSM_X4_T(r0, r1, r2, r3, addr)                                      \
    asm volatile("ldmatrix.sync.aligned.m8n8.x4.trans.shared.b16 {%0,%1,%2,%3}, [%4];" \
                 : "=r"(r0), "=r"(r1), "=r"(r2), "=r"(r3) : "r"(addr))

#define MMA_F16(d, a, b0, b1)                                                \
    asm volatile("mma.sync.aligned.m16n8k16.row.col.f32.f16.f16.f32 "        \
                 "{%0,%1,%2,%3}, {%4,%5,%6,%7}, {%8,%9}, {%0,%1,%2,%3};"     \
                 : "+f"((d)[0]), "+f"((d)[1]), "+f"((d)[2]), "+f"((d)[3])    \
                 : "r"((a)[0]), "r"((a)[1]), "r"((a)[2]), "r"((a)[3]),       \
                   "r"(b0), "r"(b1))

__device__ __forceinline__ uint32_t f2h2(float a, float b) {
    __half2 t = __floats2half2_rn(a, b);
    return *reinterpret_cast<uint32_t*>(&t);
}
__device__ __forceinline__ uint32_t ex2h2(float a, float b) {
    uint32_t x = f2h2(a, b), r;
    asm("ex2.approx.f16x2 %0, %1;" : "=r"(r) : "r"(x));
    return r;
}

// ---------------------------------------------------------------------------
// Conversion kernels
// ---------------------------------------------------------------------------
__global__ void convert_h_kernel(const float* __restrict__ in,
                                 __half* __restrict__ out, int n4)
{
    int i = blockIdx.x * blockDim.x + threadIdx.x;
    if (i >= n4) return;
    float4 x = ((const float4*)in)[i];
    ((uint2*)out)[i] = make_uint2(f2h2(x.x, x.y), f2h2(x.z, x.w));
}

// W[K,N] fp32 -> Wt[N,K] fp16 (tiled transpose)
__global__ void convert_w_kernel(const float* __restrict__ W,
                                 __half* __restrict__ out, int K, int N)
{
    __shared__ float t[32][33];
    int n0 = blockIdx.x * 32, k0 = blockIdx.y * 32;
    int tx = threadIdx.x, ty = threadIdx.y;  // 32 x 8
#pragma unroll
    for (int r = 0; r < 4; r++)
        t[ty + r * 8][tx] = W[(size_t)(k0 + ty + r * 8) * N + n0 + tx];
    __syncthreads();
#pragma unroll
    for (int r = 0; r < 4; r++) {
        float x = t[tx][ty + r * 8];
        out[(size_t)(n0 + ty + r * 8) * K + k0 + tx] = __float2half_rn(x);
    }
}

// ---------------------------------------------------------------------------
// mma.sync fp16 GEMM (single-A), XOR-swizzled smem, K-chunk 64.
// R10-proven 2-stage pipeline order (do NOT reorder):
//   sync -> load(c+1) -> commit -> wait1 -> sync -> compute(c)
// CTA 128x128, 256 threads (8 warps of 64x32).
// mode 0: fp32 C out.  mode 1: QKV -> Q, K, V (all row-major fp16).
// ---------------------------------------------------------------------------
#define KC       64
#define NCH      (GK / KC)           // 32
#define TILE_B   (128 * 128)         // 16384
#define STAGE_B  (2 * TILE_B)        // 32768: A, B
#define GEMM_SMEM (2 * STAGE_B)      // 65536

__global__ void __launch_bounds__(256, 2) mma_gemm_kernel(
    const __half* __restrict__ A, const __half* __restrict__ B,
    const float* __restrict__ bias, float* __restrict__ C, int N, int mode)
{
    extern __shared__ char smem[];
    const uint32_t sb = smem_u32(smem);
    const int tid = threadIdx.x;
    const int wid = tid >> 5, lane = tid & 31;
    const int n0 = blockIdx.x * 128, m0 = blockIdx.y * 128;
    const int wm = (wid & 1) * 64, wn = (wid >> 1) * 32;

    const uint32_t swx = (uint32_t)(lane & 7) << 4;
    const uint32_t arow = (uint32_t)(wm + (lane & 15)) * 128;
    const uint32_t acol = ((uint32_t)(lane >> 4) << 4);
    const uint32_t brow = (uint32_t)(wn + (lane & 7) + ((lane >> 4) << 3)) * 128;
    const uint32_t bcol = (((uint32_t)(lane >> 3) & 1) << 4);

    float acc[4][4][4];
#pragma unroll
    for (int mi = 0; mi < 4; mi++)
#pragma unroll
        for (int nj = 0; nj < 4; nj++)
#pragma unroll
            for (int d = 0; d < 4; d++) acc[mi][nj][d] = 0.f;

    auto load_chunk = [&](int c, int buf) {
        const int kk = c * KC;
        const uint32_t st = sb + buf * STAGE_B;
#pragma unroll
        for (int t = 0; t < 2; t++) {
            const int row0 = (t == 0) ? m0 : n0;
            const __half* src = (t == 0) ? A : B;
            const uint32_t dst = st + t * TILE_B;
#pragma unroll
            for (int i = 0; i < 4; i++) {
                int flat = tid + i * 256;
                int r = flat >> 3;
                int s = (flat & 7) * 16;
                uint32_t off = (uint32_t)r * 128 + (s ^ ((r & 7) << 4));
                cp_async16(dst + off,
                           (const char*)(src + (size_t)(row0 + r) * GK + kk) + s);
            }
        }
    };

    load_chunk(0, 0); CP_COMMIT();

    for (int c = 0; c < NCH; c++) {
        const int buf = c & 1;
        __syncthreads();                       // all warps done with buf^1
        if (c + 1 < NCH) load_chunk(c + 1, buf ^ 1);
        CP_COMMIT();
        CP_WAIT1();                            // own copies of chunk c done
        __syncthreads();                       // all threads' copies visible

        const uint32_t sA = sb + buf * STAGE_B;
        const uint32_t sB = sA + TILE_B;
#pragma unroll
        for (int ks = 0; ks < 4; ks++) {
            const uint32_t kc = (uint32_t)ks * 32;
            uint32_t b2[2][4];
#pragma unroll
            for (int p = 0; p < 2; p++)
                LDSM_X4(b2[p][0], b2[p][1], b2[p][2], b2[p][3],
                        sB + brow + p * (16 * 128) + ((bcol + kc) ^ swx));
#pragma unroll
            for (int mi = 0; mi < 4; mi++) {
                uint32_t a4[4];
                LDSM_X4(a4[0], a4[1], a4[2], a4[3],
                        sA + arow + mi * (16 * 128) + ((acol + kc) ^ swx));
#pragma unroll
                for (int nj = 0; nj < 4; nj++) {
                    const int p = nj >> 1, e = (nj & 1) * 2;
                    MMA_F16(acc[mi][nj], a4, b2[p][e], b2[p][e + 1]);
                }
            }
        }
    }

    // ---- epilogue ----
    const int g = lane >> 2, tg = lane & 3;
#pragma unroll
    for (int mi = 0; mi < 4; mi++) {
#pragma unroll
        for (int half = 0; half < 2; half++) {
            const int m = m0 + wm + mi * 16 + g + half * 8;
            const int bb = m >> 11, s = m & (SEQ - 1);
#pragma unroll
            for (int nj = 0; nj < 4; nj++) {
                const int col = n0 + wn + nj * 8 + tg * 2;
                float v0 = acc[mi][nj][half * 2 + 0] + __ldg(&bias[col]);
                float v1 = acc[mi][nj][half * 2 + 1] + __ldg(&bias[col + 1]);
                if (mode == 0) {
                    *(float2*)(C + (size_t)m * N + col) = make_float2(v0, v1);
                } else {
                    const int part = col >> 11;
                    const int h = (col >> 7) & (NH - 1);
                    const int d0 = col & (HD - 1);
                    const size_t idx = (((size_t)bb * NH + h) * SEQ + s) * HD + d0;
                    __half* dst = (part == 0) ? g_Q : (part == 1) ? g_K : g_V;
                    *(uint32_t*)(dst + idx) = f2h2(v0, v1);
                }
            }
        }
    }
}

// ---------------------------------------------------------------------------
// Tensor-core flash attention: causal + ALiBi in log2 domain, fp16 P via
// ex2.approx.f16x2, single-product PV (V via ldmatrix.trans of [s,d]),
// row sums via ones-MMA, DESCENDING k-tiles + ballot-skipped rescale.
// Balanced mapping: 256 CTAs, CTA j handles items j and 511-j (qt-descending
// sorted) -> every CTA does exactly 34 k-tiles, single wave.
// Output written as single fp16 into g_A (proj input).
// ---------------------------------------------------------------------------
#define QSTR 272
#define OFF_KS (128 * QSTR)            // 34816: K tile, 64 rows x 272B
#define OFF_VS (OFF_KS + 64 * QSTR)    // 52224: V tile [s,d], 64 rows x 272B
#define ATT_SMEM (OFF_VS + 64 * QSTR)  // 69632
#define ONESH2 0x3C003C00u
#define NITEMS (16 * NH * BATCH)       // 512

__global__ void __launch_bounds__(256, 2) attn_mma_kernel()
{
    extern __shared__ char smc[];
    const uint32_t sb = smem_u32(smc);
    const int tid = threadIdx.x;
    const int wid = tid >> 5, lane = tid & 31;
    const int g = lane >> 2, tg = lane & 3;
    const int WR = wid * 16;

    const uint32_t qbase = sb + (uint32_t)(WR + (lane & 15)) * QSTR + ((lane >> 4) << 4);
    const uint32_t kbase = sb + OFF_KS
        + (uint32_t)((lane & 7) + ((lane >> 4) << 3)) * QSTR + (((lane >> 3) & 1) << 4);
    // V (trans): lanes 0-7 rows s0-7 d0; 8-15 rows s8-15 d0; 16-23 rows s0-7 d+16B; 24-31 rows s8-15 d+16B
    const uint32_t vbase = sb + OFF_VS
        + (uint32_t)((lane & 7) + (((lane >> 3) & 1) << 3)) * QSTR + ((lane >> 4) << 4);

#pragma unroll 1
    for (int sel = 0; sel < 2; sel++) {
        const int it = sel ? (NITEMS - 1 - (int)blockIdx.x) : (int)blockIdx.x;
        const int qt = 15 - (it >> 5);
        const int h  = (it & 31) >> 1;
        const int b  = it & 1;
        const size_t bh = (size_t)b * NH + h;
        const int q0 = qt * 128;

        const float scale2 = (1.f / 128.f) * LOG2E;
        const float slope2 = exp2f(-0.5f * (float)(h + 1)) * LOG2E;

        // ---- stage Q ----
        {
            const __half* Q = g_Q + (bh * SEQ + q0) * HD;
#pragma unroll
            for (int i = 0; i < 8; i++) {
                int flat = tid + i * 256;
                int r = flat >> 4, cb = (flat & 15) * 16;
                cp_async16(sb + r * QSTR + cb,
                           (const char*)(Q + (size_t)r * HD) + cb);
            }
            CP_COMMIT();
        }

        float oacc[16][4];
#pragma unroll
        for (int nf = 0; nf < 16; nf++)
#pragma unroll
            for (int d = 0; d < 4; d++) oacc[nf][d] = 0.f;
        float lacc[4] = {0.f, 0.f, 0.f, 0.f};
        float m_run[2] = {-1e30f, -1e30f};

        const int nkt = 2 * qt + 2;
        for (int kt = nkt - 1; kt >= 0; kt--) {    // DESCENDING: diagonal first
            const int s0 = kt * 64;
            __syncthreads();

            {
                const __half* K = g_K + (bh * SEQ + s0) * HD;
#pragma unroll
                for (int i = 0; i < 4; i++) {
                    int flat = tid + i * 256;
                    int r = flat >> 4, cb = (flat & 15) * 16;
                    cp_async16(sb + OFF_KS + r * QSTR + cb,
                               (const char*)(K + (size_t)r * HD) + cb);
                }
                CP_COMMIT();
            }
            {
                const __half* V = g_V + (bh * SEQ + s0) * HD;
#pragma unroll
                for (int i = 0; i < 4; i++) {
                    int flat = tid + i * 256;
                    int r = flat >> 4, cb = (flat & 15) * 16;
                    cp_async16(sb + OFF_VS + r * QSTR + cb,
                               (const char*)(V + (size_t)r * HD) + cb);
                }
                CP_COMMIT();
            }
            CP_WAIT1();
            __syncthreads();

            // ---- S = Q K^T ----
            float sacc[8][4];
#pragma unroll
            for (int nf = 0; nf < 8; nf++)
#pragma unroll
                for (int d = 0; d < 4; d++) sacc[nf][d] = 0.f;

#pragma unroll
            for (int ks = 0; ks < 8; ks++) {
                uint32_t ah[4];
                LDSM_X4(ah[0], ah[1], ah[2], ah[3], qbase + ks * 32);
#pragma unroll
                for (int j = 0; j < 4; j++) {
                    uint32_t km[4];
                    LDSM_X4(km[0], km[1], km[2], km[3],
                            kbase + j * (16 * QSTR) + ks * 32);
                    MMA_F16(sacc[2 * j],     ah, km[0], km[1]);
                    MMA_F16(sacc[2 * j + 1], ah, km[2], km[3]);
                }
            }

            // ---- bias + mask (log2 domain) ----
            const int row0 = q0 + WR + g;
            const int row1 = row0 + 8;
#pragma unroll
            for (int nf = 0; nf < 8; nf++) {
                const int cbase = s0 + nf * 8 + tg * 2;
#pragma unroll
                for (int e = 0; e < 2; e++) {
                    const int col = cbase + e;
                    float v0 = fmaf(sacc[nf][e], scale2, slope2 * (float)(col - row0));
                    float v1 = fmaf(sacc[nf][2 + e], scale2, slope2 * (float)(col - row1));
                    sacc[nf][e]     = (col > row0) ? -1e30f : v0;
                    sacc[nf][2 + e] = (col > row1) ? -1e30f : v1;
                }
            }

            // ---- online max; rescale only if max moved (warp-uniform skip) ----
            float m_new[2], alpha[2];
#pragma unroll
            for (int half = 0; half < 2; half++) {
                float mx = -1e30f;
#pragma unroll
                for (int nf = 0; nf < 8; nf++)
                    mx = fmaxf(mx, fmaxf(sacc[nf][2 * half], sacc[nf][2 * half + 1]));
                mx = fmaxf(mx, __shfl_xor_sync(0xffffffffu, mx, 1));
                mx = fmaxf(mx, __shfl_xor_sync(0xffffffffu, mx, 2));
                m_new[half] = fmaxf(m_run[half], mx);
                alpha[half] = exp2f(m_run[half] - m_new[half]);
                m_run[half] = m_new[half];
            }
            const bool upd = (alpha[0] < 1.f) || (alpha[1] < 1.f);
            if (__any_sync(0xffffffffu, upd)) {
#pragma unroll
                for (int nf = 0; nf < 16; nf++) {
                    oacc[nf][0] *= alpha[0]; oacc[nf][1] *= alpha[0];
                    oacc[nf][2] *= alpha[1]; oacc[nf][3] *= alpha[1];
                }
                lacc[0] *= alpha[0]; lacc[1] *= alpha[0];
                lacc[2] *= alpha[1]; lacc[3] *= alpha[1];
            }

            // ---- P = exp2(S - m) as fp16x2 fragments ----
            uint32_t ph[8][2];
#pragma unroll
            for (int nf = 0; nf < 8; nf++) {
                ph[nf][0] = ex2h2(sacc[nf][0] - m_new[0], sacc[nf][1] - m_new[0]);
                ph[nf][1] = ex2h2(sacc[nf][2] - m_new[1], sacc[nf][3] - m_new[1]);
            }

            CP_WAIT0();
            __syncthreads();

            // ---- O += P V (V fragments via ldmatrix.trans) + ones-MMA ----
#pragma unroll
            for (int ks = 0; ks < 4; ks++) {
                uint32_t ap[4] = {ph[2 * ks][0], ph[2 * ks][1],
                                  ph[2 * ks + 1][0], ph[2 * ks + 1][1]};
                MMA_F16(lacc, ap, ONESH2, ONESH2);
#pragma unroll
                for (int j = 0; j < 8; j++) {
                    uint32_t vm[4];
                    LDSM_X4_T(vm[0], vm[1], vm[2], vm[3],
                              vbase + ks * (16 * QSTR) + j * 32);
                    MMA_F16(oacc[2 * j],     ap, vm[0], vm[1]);
                    MMA_F16(oacc[2 * j + 1], ap, vm[2], vm[3]);
                }
            }
        }

        // ---- normalize + write single fp16 O into g_A ----
        const float inv0 = 1.f / lacc[0];
        const float inv1 = 1.f / lacc[2];
#pragma unroll
        for (int nf = 0; nf < 16; nf++) {
            const int d0 = nf * 8 + tg * 2;
            {
                const int m = b * SEQ + q0 + WR + g;
                *(uint32_t*)(g_A + (size_t)m * HID + h * HD + d0) =
                    f2h2(oacc[nf][0] * inv0, oacc[nf][1] * inv0);
            }
            {
                const int m = b * SEQ + q0 + WR + g + 8;
                *(uint32_t*)(g_A + (size_t)m * HID + h * HD + d0) =
                    f2h2(oacc[nf][2] * inv1, oacc[nf][3] * inv1);
            }
        }
        __syncthreads();   // all warps done with smem before next item's Q load
    }
}

// ---------------------------------------------------------------------------
extern "C" void kernel_launch(void* const* d_in, const int* in_sizes, int n_in,
                              void* d_out, int out_size)
{
    const float* hidden = (const float*)d_in[0];
    const float* w_qkv  = (const float*)d_in[1];
    const float* b_qkv  = (const float*)d_in[2];
    const float* w_proj = (const float*)d_in[3];
    const float* b_proj = (const float*)d_in[4];
    float* out = (float*)d_out;

    void *pA, *pWq, *pWp;
    cudaGetSymbolAddress(&pA, g_A);
    cudaGetSymbolAddress(&pWq, g_Wq);
    cudaGetSymbolAddress(&pWp, g_Wp);

    cudaFuncSetAttribute(mma_gemm_kernel,
                         cudaFuncAttributeMaxDynamicSharedMemorySize, GEMM_SMEM);
    cudaFuncSetAttribute(attn_mma_kernel,
                         cudaFuncAttributeMaxDynamicSharedMemorySize, ATT_SMEM);

    // weight conversion (transpose, single fp16)
    convert_w_kernel<<<dim3(3 * HID / 32, HID / 32), dim3(32, 8)>>>(
        w_qkv, (__half*)pWq, HID, 3 * HID);
    convert_w_kernel<<<dim3(HID / 32, HID / 32), dim3(32, 8)>>>(
        w_proj, (__half*)pWp, HID, HID);

    // hidden -> fp16 (QKV GEMM A input)
    {
        int n4 = MTOT * HID / 4;
        convert_h_kernel<<<(n4 + 255) / 256, 256>>>(hidden, (__half*)pA, n4);
    }

    // QKV GEMM -> Q, K, V (fp16, all row-major)
    mma_gemm_kernel<<<dim3(3 * HID / 128, MTOT / 128), 256, GEMM_SMEM>>>(
        (const __half*)pA, (const __half*)pWq, b_qkv, nullptr, 3 * HID, 1);

    // balanced tensor-core flash attention -> g_A (fp16)
    attn_mma_kernel<<<NITEMS / 2, 256, ATT_SMEM>>>();

    // proj GEMM -> out
    mma_gemm_kernel<<<dim3(HID / 128, MTOT / 128), 256, GEMM_SMEM>>>(
        (const __half*)pA, (const __half*)pWp, b_proj, out, HID, 0);
}

// round 15
// speedup vs baseline: 1.7428x; 1.0251x over previous
#include <cuda_runtime.h>
#include <cuda_fp16.h>
#include <cstdint>

#define NH    16
#define HD    128
#define SEQ   2048
#define BATCH 2
#define HID   2048
#define MTOT  (BATCH * SEQ)   // 4096
#define GK    2048
#define LOG2E 1.4426950408889634f

// ---------------------------------------------------------------------------
// Scratch (__device__ globals — allocation-free)
// ---------------------------------------------------------------------------
__device__ __half g_Q[(size_t)BATCH * NH * SEQ * HD];  // Q [b,h,s,d]
__device__ __half g_K[(size_t)BATCH * NH * SEQ * HD];  // K [b,h,s,d]
__device__ __half g_V[(size_t)BATCH * NH * SEQ * HD];  // V [b,h,s,d]

__device__ __half g_A [(size_t)MTOT * HID];      // GEMM A (hidden / attn-out)
__device__ __half g_Wq[(size_t)3 * HID * HID];   // w_qkv^T fp16 [N,K]
__device__ __half g_Wp[(size_t)HID * HID];       // w_proj^T fp16 [N,K]

// ---------------------------------------------------------------------------
// helpers
// ---------------------------------------------------------------------------
__device__ __forceinline__ uint32_t smem_u32(const void* p) {
    uint32_t a;
    asm("{ .reg .u64 t; cvta.to.shared.u64 t, %1; cvt.u32.u64 %0, t; }"
        : "=r"(a) : "l"(p));
    return a;
}
__device__ __forceinline__ void cp_async16(uint32_t dst, const void* src) {
    asm volatile("cp.async.cg.shared.global [%0], [%1], 16;\n"
                 :: "r"(dst), "l"(src));
}
#define CP_COMMIT() asm volatile("cp.async.commit_group;\n" ::: "memory")
#define CP_WAIT1()  asm volatile("cp.async.wait_group 1;\n" ::: "memory")
#define CP_WAIT0()  asm volatile("cp.async.wait_group 0;\n" ::: "memory")

#define LDSM_X4(r0, r1, r2, r3, addr)                                        \
    asm volatile("ldmatrix.sync.aligned.m8n8.x4.shared.b16 {%0,%1,%2,%3}, [%4];" \
                 : "=r"(r0), "=r"(r1), "=r"(r2), "=r"(r3) : "r"(addr))

#define LDSM_X4_T(r0, r1, r2, r3, addr)                                      \
    asm volatile("ldmatrix.sync.aligned.m8n8.x4.trans.shared.b16 {%0,%1,%2,%3}, [%4];" \
                 : "=r"(r0), "=r"(r1), "=r"(r2), "=r"(r3) : "r"(addr))

#define MMA_F16(d, a, b0, b1)                                                \
    asm volatile("mma.sync.aligned.m16n8k16.row.col.f32.f16.f16.f32 "        \
                 "{%0,%1,%2,%3}, {%4,%5,%6,%7}, {%8,%9}, {%0,%1,%2,%3};"     \
                 : "+f"((d)[0]), "+f"((d)[1]), "+f"((d)[2]), "+f"((d)[3])    \
                 : "r"((a)[0]), "r"((a)[1]), "r"((a)[2]), "r"((a)[3]),       \
                   "r"(b0), "r"(b1))

__device__ __forceinline__ uint32_t f2h2(float a, float b) {
    __half2 t = __floats2half2_rn(a, b);
    return *reinterpret_cast<uint32_t*>(&t);
}
__device__ __forceinline__ uint32_t ex2h2(float a, float b) {
    uint32_t x = f2h2(a, b), r;
    asm("ex2.approx.f16x2 %0, %1;" : "=r"(r) : "r"(x));
    return r;
}

// ---------------------------------------------------------------------------
// Conversion kernels
// ---------------------------------------------------------------------------
__global__ void convert_h_kernel(const float* __restrict__ in,
                                 __half* __restrict__ out, int n4)
{
    int i = blockIdx.x * blockDim.x + threadIdx.x;
    if (i >= n4) return;
    float4 x = ((const float4*)in)[i];
    ((uint2*)out)[i] = make_uint2(f2h2(x.x, x.y), f2h2(x.z, x.w));
}

// W[K,N] fp32 -> Wt[N,K] fp16 (tiled transpose)
__global__ void convert_w_kernel(const float* __restrict__ W,
                                 __half* __restrict__ out, int K, int N)
{
    __shared__ float t[32][33];
    int n0 = blockIdx.x * 32, k0 = blockIdx.y * 32;
    int tx = threadIdx.x, ty = threadIdx.y;  // 32 x 8
#pragma unroll
    for (int r = 0; r < 4; r++)
        t[ty + r * 8][tx] = W[(size_t)(k0 + ty + r * 8) * N + n0 + tx];
    __syncthreads();
#pragma unroll
    for (int r = 0; r < 4; r++) {
        float x = t[tx][ty + r * 8];
        out[(size_t)(n0 + ty + r * 8) * K + k0 + tx] = __float2half_rn(x);
    }
}

// ---------------------------------------------------------------------------
// mma.sync fp16 GEMM (single-A), XOR-swizzled smem, K-chunk 64.
// CTA tile 128x64, 128 threads (4 warps, 2x2 of 64x32) -> 4 CTAs/SM:
// smaller barrier domains keep 12 of 16 warps running through each sync.
// R10-proven 2-stage pipeline order (do NOT reorder):
//   sync -> load(c+1) -> commit -> wait1 -> sync -> compute(c)
// mode 0: fp32 C out.  mode 1: QKV -> Q, K, V (all row-major fp16).
// ---------------------------------------------------------------------------
#define KC       64
#define NCH      (GK / KC)           // 32
#define ATILE_B  (128 * 128)         // 16384: A 128 rows x 128B
#define BTILE_B  (64 * 128)          // 8192:  B 64 rows x 128B
#define STAGE_B  (ATILE_B + BTILE_B) // 24576
#define GEMM_SMEM (2 * STAGE_B)      // 49152 -> 4 CTAs/SM

__global__ void __launch_bounds__(128, 4) mma_gemm_kernel(
    const __half* __restrict__ A, const __half* __restrict__ B,
    const float* __restrict__ bias, float* __restrict__ C, int N, int mode)
{
    extern __shared__ char smem[];
    const uint32_t sb = smem_u32(smem);
    const int tid = threadIdx.x;
    const int wid = tid >> 5, lane = tid & 31;
    const int n0 = blockIdx.x * 64, m0 = blockIdx.y * 128;
    const int wm = (wid & 1) * 64, wn = (wid >> 1) * 32;

    const uint32_t swx = (uint32_t)(lane & 7) << 4;
    const uint32_t arow = (uint32_t)(wm + (lane & 15)) * 128;
    const uint32_t acol = ((uint32_t)(lane >> 4) << 4);
    const uint32_t brow = (uint32_t)(wn + (lane & 7) + ((lane >> 4) << 3)) * 128;
    const uint32_t bcol = (((uint32_t)(lane >> 3) & 1) << 4);

    float acc[4][4][4];
#pragma unroll
    for (int mi = 0; mi < 4; mi++)
#pragma unroll
        for (int nj = 0; nj < 4; nj++)
#pragma unroll
            for (int d = 0; d < 4; d++) acc[mi][nj][d] = 0.f;

    auto load_chunk = [&](int c, int buf) {
        const int kk = c * KC;
        const uint32_t st = sb + buf * STAGE_B;
        // A: 128 rows x 128B = 1024 x 16B -> 8 per thread
#pragma unroll
        for (int i = 0; i < 8; i++) {
            int flat = tid + i * 128;
            int r = flat >> 3;
            int s = (flat & 7) * 16;
            uint32_t off = (uint32_t)r * 128 + (s ^ ((r & 7) << 4));
            cp_async16(st + off,
                       (const char*)(A + (size_t)(m0 + r) * GK + kk) + s);
        }
        // B: 64 rows x 128B = 512 x 16B -> 4 per thread
#pragma unroll
        for (int i = 0; i < 4; i++) {
            int flat = tid + i * 128;
            int r = flat >> 3;
            int s = (flat & 7) * 16;
            uint32_t off = (uint32_t)r * 128 + (s ^ ((r & 7) << 4));
            cp_async16(st + ATILE_B + off,
                       (const char*)(B + (size_t)(n0 + r) * GK + kk) + s);
        }
    };

    load_chunk(0, 0); CP_COMMIT();

    for (int c = 0; c < NCH; c++) {
        const int buf = c & 1;
        __syncthreads();                       // all warps done with buf^1
        if (c + 1 < NCH) load_chunk(c + 1, buf ^ 1);
        CP_COMMIT();
        CP_WAIT1();                            // own copies of chunk c done
        __syncthreads();                       // all threads' copies visible

        const uint32_t sA = sb + buf * STAGE_B;
        const uint32_t sB = sA + ATILE_B;
#pragma unroll
        for (int ks = 0; ks < 4; ks++) {
            const uint32_t kc = (uint32_t)ks * 32;
            uint32_t b2[2][4];
#pragma unroll
            for (int p = 0; p < 2; p++)
                LDSM_X4(b2[p][0], b2[p][1], b2[p][2], b2[p][3],
                        sB + brow + p * (16 * 128) + ((bcol + kc) ^ swx));
#pragma unroll
            for (int mi = 0; mi < 4; mi++) {
                uint32_t a4[4];
                LDSM_X4(a4[0], a4[1], a4[2], a4[3],
                        sA + arow + mi * (16 * 128) + ((acol + kc) ^ swx));
#pragma unroll
                for (int nj = 0; nj < 4; nj++) {
                    const int p = nj >> 1, e = (nj & 1) * 2;
                    MMA_F16(acc[mi][nj], a4, b2[p][e], b2[p][e + 1]);
                }
            }
        }
    }

    // ---- epilogue ----
    const int g = lane >> 2, tg = lane & 3;
#pragma unroll
    for (int mi = 0; mi < 4; mi++) {
#pragma unroll
        for (int half = 0; half < 2; half++) {
            const int m = m0 + wm + mi * 16 + g + half * 8;
            const int bb = m >> 11, s = m & (SEQ - 1);
#pragma unroll
            for (int nj = 0; nj < 4; nj++) {
                const int col = n0 + wn + nj * 8 + tg * 2;
                float v0 = acc[mi][nj][half * 2 + 0] + __ldg(&bias[col]);
                float v1 = acc[mi][nj][half * 2 + 1] + __ldg(&bias[col + 1]);
                if (mode == 0) {
                    *(float2*)(C + (size_t)m * N + col) = make_float2(v0, v1);
                } else {
                    const int part = col >> 11;
                    const int h = (col >> 7) & (NH - 1);
                    const int d0 = col & (HD - 1);
                    const size_t idx = (((size_t)bb * NH + h) * SEQ + s) * HD + d0;
                    __half* dst = (part == 0) ? g_Q : (part == 1) ? g_K : g_V;
                    *(uint32_t*)(dst + idx) = f2h2(v0, v1);
                }
            }
        }
    }
}

// ---------------------------------------------------------------------------
// Tensor-core flash attention (unchanged from R14): causal + ALiBi log2,
// fp16 P via ex2.approx.f16x2, single-product PV (V via ldmatrix.trans),
// ones-MMA row sums, descending k-tiles + ballot-skipped rescale, balanced
// 256-CTA pairing (items j and 511-j), single fp16 output into g_A.
// ---------------------------------------------------------------------------
#define QSTR 272
#define OFF_KS (128 * QSTR)
#define OFF_VS (OFF_KS + 64 * QSTR)
#define ATT_SMEM (OFF_VS + 64 * QSTR)  // 69632
#define ONESH2 0x3C003C00u
#define NITEMS (16 * NH * BATCH)       // 512

__global__ void __launch_bounds__(256, 2) attn_mma_kernel()
{
    extern __shared__ char smc[];
    const uint32_t sb = smem_u32(smc);
    const int tid = threadIdx.x;
    const int wid = tid >> 5, lane = tid & 31;
    const int g = lane >> 2, tg = lane & 3;
    const int WR = wid * 16;

    const uint32_t qbase = sb + (uint32_t)(WR + (lane & 15)) * QSTR + ((lane >> 4) << 4);
    const uint32_t kbase = sb + OFF_KS
        + (uint32_t)((lane & 7) + ((lane >> 4) << 3)) * QSTR + (((lane >> 3) & 1) << 4);
    const uint32_t vbase = sb + OFF_VS
        + (uint32_t)((lane & 7) + (((lane >> 3) & 1) << 3)) * QSTR + ((lane >> 4) << 4);

#pragma unroll 1
    for (int sel = 0; sel < 2; sel++) {
        const int it = sel ? (NITEMS - 1 - (int)blockIdx.x) : (int)blockIdx.x;
        const int qt = 15 - (it >> 5);
        const int h  = (it & 31) >> 1;
        const int b  = it & 1;
        const size_t bh = (size_t)b * NH + h;
        const int q0 = qt * 128;

        const float scale2 = (1.f / 128.f) * LOG2E;
        const float slope2 = exp2f(-0.5f * (float)(h + 1)) * LOG2E;

        {
            const __half* Q = g_Q + (bh * SEQ + q0) * HD;
#pragma unroll
            for (int i = 0; i < 8; i++) {
                int flat = tid + i * 256;
                int r = flat >> 4, cb = (flat & 15) * 16;
                cp_async16(sb + r * QSTR + cb,
                           (const char*)(Q + (size_t)r * HD) + cb);
            }
            CP_COMMIT();
        }

        float oacc[16][4];
#pragma unroll
        for (int nf = 0; nf < 16; nf++)
#pragma unroll
            for (int d = 0; d < 4; d++) oacc[nf][d] = 0.f;
        float lacc[4] = {0.f, 0.f, 0.f, 0.f};
        float m_run[2] = {-1e30f, -1e30f};

        const int nkt = 2 * qt + 2;
        for (int kt = nkt - 1; kt >= 0; kt--) {
            const int s0 = kt * 64;
            __syncthreads();

            {
                const __half* K = g_K + (bh * SEQ + s0) * HD;
#pragma unroll
                for (int i = 0; i < 4; i++) {
                    int flat = tid + i * 256;
                    int r = flat >> 4, cb = (flat & 15) * 16;
                    cp_async16(sb + OFF_KS + r * QSTR + cb,
                               (const char*)(K + (size_t)r * HD) + cb);
                }
                CP_COMMIT();
            }
            {
                const __half* V = g_V + (bh * SEQ + s0) * HD;
#pragma unroll
                for (int i = 0; i < 4; i++) {
                    int flat = tid + i * 256;
                    int r = flat >> 4, cb = (flat & 15) * 16;
                    cp_async16(sb + OFF_VS + r * QSTR + cb,
                               (const char*)(V + (size_t)r * HD) + cb);
                }
                CP_COMMIT();
            }
            CP_WAIT1();
            __syncthreads();

            float sacc[8][4];
#pragma unroll
            for (int nf = 0; nf < 8; nf++)
#pragma unroll
                for (int d = 0; d < 4; d++) sacc[nf][d] = 0.f;

#pragma unroll
            for (int ks = 0; ks < 8; ks++) {
                uint32_t ah[4];
                LDSM_X4(ah[0], ah[1], ah[2], ah[3], qbase + ks * 32);
#pragma unroll
                for (int j = 0; j < 4; j++) {
                    uint32_t km[4];
                    LDSM_X4(km[0], km[1], km[2], km[3],
                            kbase + j * (16 * QSTR) + ks * 32);
                    MMA_F16(sacc[2 * j],     ah, km[0], km[1]);
                    MMA_F16(sacc[2 * j + 1], ah, km[2], km[3]);
                }
            }

            const int row0 = q0 + WR + g;
            const int row1 = row0 + 8;
#pragma unroll
            for (int nf = 0; nf < 8; nf++) {
                const int cbase = s0 + nf * 8 + tg * 2;
#pragma unroll
                for (int e = 0; e < 2; e++) {
                    const int col = cbase + e;
                    float v0 = fmaf(sacc[nf][e], scale2, slope2 * (float)(col - row0));
                    float v1 = fmaf(sacc[nf][2 + e], scale2, slope2 * (float)(col - row1));
                    sacc[nf][e]     = (col > row0) ? -1e30f : v0;
                    sacc[nf][2 + e] = (col > row1) ? -1e30f : v1;
                }
            }

            float m_new[2], alpha[2];
#pragma unroll
            for (int half = 0; half < 2; half++) {
                float mx = -1e30f;
#pragma unroll
                for (int nf = 0; nf < 8; nf++)
                    mx = fmaxf(mx, fmaxf(sacc[nf][2 * half], sacc[nf][2 * half + 1]));
                mx = fmaxf(mx, __shfl_xor_sync(0xffffffffu, mx, 1));
                mx = fmaxf(mx, __shfl_xor_sync(0xffffffffu, mx, 2));
                m_new[half] = fmaxf(m_run[half], mx);
                alpha[half] = exp2f(m_run[half] - m_new[half]);
                m_run[half] = m_new[half];
            }
            const bool upd = (alpha[0] < 1.f) || (alpha[1] < 1.f);
            if (__any_sync(0xffffffffu, upd)) {
#pragma unroll
                for (int nf = 0; nf < 16; nf++) {
                    oacc[nf][0] *= alpha[0]; oacc[nf][1] *= alpha[0];
                    oacc[nf][2] *= alpha[1]; oacc[nf][3] *= alpha[1];
                }
                lacc[0] *= alpha[0]; lacc[1] *= alpha[0];
                lacc[2] *= alpha[1]; lacc[3] *= alpha[1];
            }

            uint32_t ph[8][2];
#pragma unroll
            for (int nf = 0; nf < 8; nf++) {
                ph[nf][0] = ex2h2(sacc[nf][0] - m_new[0], sacc[nf][1] - m_new[0]);
                ph[nf][1] = ex2h2(sacc[nf][2] - m_new[1], sacc[nf][3] - m_new[1]);
            }

            CP_WAIT0();
            __syncthreads();

#pragma unroll
            for (int ks = 0; ks < 4; ks++) {
                uint32_t ap[4] = {ph[2 * ks][0], ph[2 * ks][1],
                                  ph[2 * ks + 1][0], ph[2 * ks + 1][1]};
                MMA_F16(lacc, ap, ONESH2, ONESH2);
#pragma unroll
                for (int j = 0; j < 8; j++) {
                    uint32_t vm[4];
                    LDSM_X4_T(vm[0], vm[1], vm[2], vm[3],
                              vbase + ks * (16 * QSTR) + j * 32);
                    MMA_F16(oacc[2 * j],     ap, vm[0], vm[1]);
                    MMA_F16(oacc[2 * j + 1], ap, vm[2], vm[3]);
                }
            }
        }

        const float inv0 = 1.f / lacc[0];
        const float inv1 = 1.f / lacc[2];
#pragma unroll
        for (int nf = 0; nf < 16; nf++) {
            const int d0 = nf * 8 + tg * 2;
            {
                const int m = b * SEQ + q0 + WR + g;
                *(uint32_t*)(g_A + (size_t)m * HID + h * HD + d0) =
                    f2h2(oacc[nf][0] * inv0, oacc[nf][1] * inv0);
            }
            {
                const int m = b * SEQ + q0 + WR + g + 8;
                *(uint32_t*)(g_A + (size_t)m * HID + h * HD + d0) =
                    f2h2(oacc[nf][2] * inv1, oacc[nf][3] * inv1);
            }
        }
        __syncthreads();
    }
}

// ---------------------------------------------------------------------------
extern "C" void kernel_launch(void* const* d_in, const int* in_sizes, int n_in,
                              void* d_out, int out_size)
{
    const float* hidden = (const float*)d_in[0];
    const float* w_qkv  = (const float*)d_in[1];
    const float* b_qkv  = (const float*)d_in[2];
    const float* w_proj = (const float*)d_in[3];
    const float* b_proj = (const float*)d_in[4];
    float* out = (float*)d_out;

    void *pA, *pWq, *pWp;
    cudaGetSymbolAddress(&pA, g_A);
    cudaGetSymbolAddress(&pWq, g_Wq);
    cudaGetSymbolAddress(&pWp, g_Wp);

    cudaFuncSetAttribute(mma_gemm_kernel,
                         cudaFuncAttributeMaxDynamicSharedMemorySize, GEMM_SMEM);
    cudaFuncSetAttribute(attn_mma_kernel,
                         cudaFuncAttributeMaxDynamicSharedMemorySize, ATT_SMEM);

    // weight conversion (transpose, single fp16)
    convert_w_kernel<<<dim3(3 * HID / 32, HID / 32), dim3(32, 8)>>>(
        w_qkv, (__half*)pWq, HID, 3 * HID);
    convert_w_kernel<<<dim3(HID / 32, HID / 32), dim3(32, 8)>>>(
        w_proj, (__half*)pWp, HID, HID);

    // hidden -> fp16 (QKV GEMM A input)
    {
        int n4 = MTOT * HID / 4;
        convert_h_kernel<<<(n4 + 255) / 256, 256>>>(hidden, (__half*)pA, n4);
    }

    // QKV GEMM -> Q, K, V (fp16, row-major)
    mma_gemm_kernel<<<dim3(3 * HID / 64, MTOT / 128), 128, GEMM_SMEM>>>(
        (const __half*)pA, (const __half*)pWq, b_qkv, nullptr, 3 * HID, 1);

    // balanced tensor-core flash attention -> g_A (fp16)
    attn_mma_kernel<<<NITEMS / 2, 256, ATT_SMEM>>>();

    // proj GEMM -> out
    mma_gemm_kernel<<<dim3(HID / 64, MTOT / 128), 128, GEMM_SMEM>>>(
        (const __half*)pA, (const __half*)pWp, b_proj, out, HID, 0);
}

// round 16
// speedup vs baseline: 1.7585x; 1.0090x over previous
#include <cuda_runtime.h>
#include <cuda_fp16.h>
#include <cstdint>

#define NH    16
#define HD    128
#define SEQ   2048
#define BATCH 2
#define HID   2048
#define MTOT  (BATCH * SEQ)   // 4096
#define GK    2048
#define LOG2E 1.4426950408889634f

// ---------------------------------------------------------------------------
// Scratch (__device__ globals — allocation-free)
// ---------------------------------------------------------------------------
__device__ __half g_Q[(size_t)BATCH * NH * SEQ * HD];  // Q [b,h,s,d]
__device__ __half g_K[(size_t)BATCH * NH * SEQ * HD];  // K [b,h,s,d]
__device__ __half g_V[(size_t)BATCH * NH * SEQ * HD];  // V [b,h,s,d]

__device__ __half g_A [(size_t)MTOT * HID];      // GEMM A (hidden / attn-out)
__device__ __half g_Wq[(size_t)3 * HID * HID];   // w_qkv^T fp16 [N,K]
__device__ __half g_Wp[(size_t)HID * HID];       // w_proj^T fp16 [N,K]

// ---------------------------------------------------------------------------
// helpers
// ---------------------------------------------------------------------------
__device__ __forceinline__ uint32_t smem_u32(const void* p) {
    uint32_t a;
    asm("{ .reg .u64 t; cvta.to.shared.u64 t, %1; cvt.u32.u64 %0, t; }"
        : "=r"(a) : "l"(p));
    return a;
}
__device__ __forceinline__ void cp_async16(uint32_t dst, const void* src) {
    asm volatile("cp.async.cg.shared.global [%0], [%1], 16;\n"
                 :: "r"(dst), "l"(src));
}
#define CP_COMMIT() asm volatile("cp.async.commit_group;\n" ::: "memory")
#define CP_WAIT1()  asm volatile("cp.async.wait_group 1;\n" ::: "memory")
#define CP_WAIT0()  asm volatile("cp.async.wait_group 0;\n" ::: "memory")

#define LDSM_X4(r0, r1, r2, r3, addr)                                        \
    asm volatile("ldmatrix.sync.aligned.m8n8.x4.shared.b16 {%0,%1,%2,%3}, [%4];" \
                 : "=r"(r0), "=r"(r1), "=r"(r2), "=r"(r3) : "r"(addr))

#define LDSM_X4_T(r0, r1, r2, r3, addr)                                      \
    asm volatile("ldmatrix.sync.aligned.m8n8.x4.trans.shared.b16 {%0,%1,%2,%3}, [%4];" \
                 : "=r"(r0), "=r"(r1), "=r"(r2), "=r"(r3) : "r"(addr))

#define MMA_F16(d, a, b0, b1)                                                \
    asm volatile("mma.sync.aligned.m16n8k16.row.col.f32.f16.f16.f32 "        \
                 "{%0,%1,%2,%3}, {%4,%5,%6,%7}, {%8,%9}, {%0,%1,%2,%3};"     \
                 : "+f"((d)[0]), "+f"((d)[1]), "+f"((d)[2]), "+f"((d)[3])    \
                 : "r"((a)[0]), "r"((a)[1]), "r"((a)[2]), "r"((a)[3]),       \
                   "r"(b0), "r"(b1))

__device__ __forceinline__ uint32_t f2h2(float a, float b) {
    __half2 t = __floats2half2_rn(a, b);
    return *reinterpret_cast<uint32_t*>(&t);
}
__device__ __forceinline__ uint32_t ex2h2(float a, float b) {
    uint32_t x = f2h2(a, b), r;
    asm("ex2.approx.f16x2 %0, %1;" : "=r"(r) : "r"(x));
    return r;
}

// ---------------------------------------------------------------------------
// Conversion kernels
// ---------------------------------------------------------------------------
__global__ void convert_h_kernel(const float* __restrict__ in,
                                 __half* __restrict__ out, int n4)
{
    int i = blockIdx.x * blockDim.x + threadIdx.x;
    if (i >= n4) return;
    float4 x = ((const float4*)in)[i];
    ((uint2*)out)[i] = make_uint2(f2h2(x.x, x.y), f2h2(x.z, x.w));
}

// W[K,N] fp32 -> Wt[N,K] fp16 (tiled transpose)
__global__ void convert_w_kernel(const float* __restrict__ W,
                                 __half* __restrict__ out, int K, int N)
{
    __shared__ float t[32][33];
    int n0 = blockIdx.x * 32, k0 = blockIdx.y * 32;
    int tx = threadIdx.x, ty = threadIdx.y;  // 32 x 8
#pragma unroll
    for (int r = 0; r < 4; r++)
        t[ty + r * 8][tx] = W[(size_t)(k0 + ty + r * 8) * N + n0 + tx];
    __syncthreads();
#pragma unroll
    for (int r = 0; r < 4; r++) {
        float x = t[tx][ty + r * 8];
        out[(size_t)(n0 + ty + r * 8) * K + k0 + tx] = __float2half_rn(x);
    }
}

// ---------------------------------------------------------------------------
// mma.sync fp16 GEMM (single-A), XOR-swizzled smem, K-chunk 64.
// CTA tile 128x64, 128 threads (4 warps, 2x2 of 64x32) -> 4 CTAs/SM.
// R10-proven 2-stage pipeline order (do NOT reorder):
//   sync -> load(c+1) -> commit -> wait1 -> sync -> compute(c)
// mode 0: fp32 C out.  mode 1: QKV -> Q, K, V (all row-major fp16).
// ---------------------------------------------------------------------------
#define KC       64
#define NCH      (GK / KC)           // 32
#define ATILE_B  (128 * 128)         // 16384
#define BTILE_B  (64 * 128)          // 8192
#define STAGE_B  (ATILE_B + BTILE_B) // 24576
#define GEMM_SMEM (2 * STAGE_B)      // 49152 -> 4 CTAs/SM

__global__ void __launch_bounds__(128, 4) mma_gemm_kernel(
    const __half* __restrict__ A, const __half* __restrict__ B,
    const float* __restrict__ bias, float* __restrict__ C, int N, int mode)
{
    extern __shared__ char smem[];
    const uint32_t sb = smem_u32(smem);
    const int tid = threadIdx.x;
    const int wid = tid >> 5, lane = tid & 31;
    const int n0 = blockIdx.x * 64, m0 = blockIdx.y * 128;
    const int wm = (wid & 1) * 64, wn = (wid >> 1) * 32;

    const uint32_t swx = (uint32_t)(lane & 7) << 4;
    const uint32_t arow = (uint32_t)(wm + (lane & 15)) * 128;
    const uint32_t acol = ((uint32_t)(lane >> 4) << 4);
    const uint32_t brow = (uint32_t)(wn + (lane & 7) + ((lane >> 4) << 3)) * 128;
    const uint32_t bcol = (((uint32_t)(lane >> 3) & 1) << 4);

    float acc[4][4][4];
#pragma unroll
    for (int mi = 0; mi < 4; mi++)
#pragma unroll
        for (int nj = 0; nj < 4; nj++)
#pragma unroll
            for (int d = 0; d < 4; d++) acc[mi][nj][d] = 0.f;

    auto load_chunk = [&](int c, int buf) {
        const int kk = c * KC;
        const uint32_t st = sb + buf * STAGE_B;
#pragma unroll
        for (int i = 0; i < 8; i++) {
            int flat = tid + i * 128;
            int r = flat >> 3;
            int s = (flat & 7) * 16;
            uint32_t off = (uint32_t)r * 128 + (s ^ ((r & 7) << 4));
            cp_async16(st + off,
                       (const char*)(A + (size_t)(m0 + r) * GK + kk) + s);
        }
#pragma unroll
        for (int i = 0; i < 4; i++) {
            int flat = tid + i * 128;
            int r = flat >> 3;
            int s = (flat & 7) * 16;
            uint32_t off = (uint32_t)r * 128 + (s ^ ((r & 7) << 4));
            cp_async16(st + ATILE_B + off,
                       (const char*)(B + (size_t)(n0 + r) * GK + kk) + s);
        }
    };

    load_chunk(0, 0); CP_COMMIT();

    for (int c = 0; c < NCH; c++) {
        const int buf = c & 1;
        __syncthreads();
        if (c + 1 < NCH) load_chunk(c + 1, buf ^ 1);
        CP_COMMIT();
        CP_WAIT1();
        __syncthreads();

        const uint32_t sA = sb + buf * STAGE_B;
        const uint32_t sB = sA + ATILE_B;
#pragma unroll
        for (int ks = 0; ks < 4; ks++) {
            const uint32_t kc = (uint32_t)ks * 32;
            uint32_t b2[2][4];
#pragma unroll
            for (int p = 0; p < 2; p++)
                LDSM_X4(b2[p][0], b2[p][1], b2[p][2], b2[p][3],
                        sB + brow + p * (16 * 128) + ((bcol + kc) ^ swx));
#pragma unroll
            for (int mi = 0; mi < 4; mi++) {
                uint32_t a4[4];
                LDSM_X4(a4[0], a4[1], a4[2], a4[3],
                        sA + arow + mi * (16 * 128) + ((acol + kc) ^ swx));
#pragma unroll
                for (int nj = 0; nj < 4; nj++) {
                    const int p = nj >> 1, e = (nj & 1) * 2;
                    MMA_F16(acc[mi][nj], a4, b2[p][e], b2[p][e + 1]);
                }
            }
        }
    }

    // ---- epilogue ----
    const int g = lane >> 2, tg = lane & 3;
#pragma unroll
    for (int mi = 0; mi < 4; mi++) {
#pragma unroll
        for (int half = 0; half < 2; half++) {
            const int m = m0 + wm + mi * 16 + g + half * 8;
            const int bb = m >> 11, s = m & (SEQ - 1);
#pragma unroll
            for (int nj = 0; nj < 4; nj++) {
                const int col = n0 + wn + nj * 8 + tg * 2;
                float v0 = acc[mi][nj][half * 2 + 0] + __ldg(&bias[col]);
                float v1 = acc[mi][nj][half * 2 + 1] + __ldg(&bias[col + 1]);
                if (mode == 0) {
                    *(float2*)(C + (size_t)m * N + col) = make_float2(v0, v1);
                } else {
                    const int part = col >> 11;
                    const int h = (col >> 7) & (NH - 1);
                    const int d0 = col & (HD - 1);
                    const size_t idx = (((size_t)bb * NH + h) * SEQ + s) * HD + d0;
                    __half* dst = (part == 0) ? g_Q : (part == 1) ? g_K : g_V;
                    *(uint32_t*)(dst + idx) = f2h2(v0, v1);
                }
            }
        }
    }
}

// ---------------------------------------------------------------------------
// Tensor-core flash attention: causal + ALiBi log2, fp16 P via ex2.f16x2,
// single-product PV (V via ldmatrix.trans), ones-MMA row sums, descending
// k-tiles + ballot-skipped rescale, balanced 256-CTA pairing.
// NEW: double-buffered K/V tiles — per tile:
//   sync -> load(next, buf^1) -> commit -> wait1 -> sync -> compute(buf)
// (one cp.async group per tile, so wait1 proves K AND V of the current
//  tile resident; the old mid-tile wait0+sync is gone.)
// ---------------------------------------------------------------------------
#define QSTR 272
#define OFF_KV (128 * QSTR)              // Q occupies [0, OFF_KV)
#define KVBUF_B (128 * QSTR)             // K rows 0-63, V rows 64-127
#define ATT_SMEM (OFF_KV + 2 * KVBUF_B)  // 104448 -> 2 CTAs/SM
#define ONESH2 0x3C003C00u
#define NITEMS (16 * NH * BATCH)         // 512

__global__ void __launch_bounds__(256, 2) attn_mma_kernel()
{
    extern __shared__ char smc[];
    const uint32_t sb = smem_u32(smc);
    const int tid = threadIdx.x;
    const int wid = tid >> 5, lane = tid & 31;
    const int g = lane >> 2, tg = lane & 3;
    const int WR = wid * 16;

    const uint32_t qbase = sb + (uint32_t)(WR + (lane & 15)) * QSTR + ((lane >> 4) << 4);
    // per-lane offsets relative to a KV buffer base
    const uint32_t klane = (uint32_t)((lane & 7) + ((lane >> 4) << 3)) * QSTR
                         + (((lane >> 3) & 1) << 4);
    const uint32_t vlane = (uint32_t)(64 * QSTR)
                         + (uint32_t)((lane & 7) + (((lane >> 3) & 1) << 3)) * QSTR
                         + ((lane >> 4) << 4);

#pragma unroll 1
    for (int sel = 0; sel < 2; sel++) {
        const int it = sel ? (NITEMS - 1 - (int)blockIdx.x) : (int)blockIdx.x;
        const int qt = 15 - (it >> 5);
        const int h  = (it & 31) >> 1;
        const int b  = it & 1;
        const size_t bh = (size_t)b * NH + h;
        const int q0 = qt * 128;
        const int nkt = 2 * qt + 2;

        const float scale2 = (1.f / 128.f) * LOG2E;
        const float slope2 = exp2f(-0.5f * (float)(h + 1)) * LOG2E;

        // KV tile loader: tile index kt into buffer buf (one group's worth)
        auto load_kv = [&](int kt, int buf) {
            const int s0 = kt * 64;
            const uint32_t base = sb + OFF_KV + (uint32_t)buf * KVBUF_B;
            const __half* K = g_K + (bh * SEQ + s0) * HD;
            const __half* V = g_V + (bh * SEQ + s0) * HD;
#pragma unroll
            for (int i = 0; i < 4; i++) {
                int flat = tid + i * 256;
                int r = flat >> 4, cb = (flat & 15) * 16;
                cp_async16(base + r * QSTR + cb,
                           (const char*)(K + (size_t)r * HD) + cb);
            }
#pragma unroll
            for (int i = 0; i < 4; i++) {
                int flat = tid + i * 256;
                int r = flat >> 4, cb = (flat & 15) * 16;
                cp_async16(base + 64 * QSTR + r * QSTR + cb,
                           (const char*)(V + (size_t)r * HD) + cb);
            }
        };

        // ---- stage Q + first KV tile (descending: diagonal first) ----
        {
            const __half* Q = g_Q + (bh * SEQ + q0) * HD;
#pragma unroll
            for (int i = 0; i < 8; i++) {
                int flat = tid + i * 256;
                int r = flat >> 4, cb = (flat & 15) * 16;
                cp_async16(sb + r * QSTR + cb,
                           (const char*)(Q + (size_t)r * HD) + cb);
            }
            CP_COMMIT();
        }
        load_kv(nkt - 1, 0);
        CP_COMMIT();

        float oacc[16][4];
#pragma unroll
        for (int nf = 0; nf < 16; nf++)
#pragma unroll
            for (int d = 0; d < 4; d++) oacc[nf][d] = 0.f;
        float lacc[4] = {0.f, 0.f, 0.f, 0.f};
        float m_run[2] = {-1e30f, -1e30f};

        for (int t = 0; t < nkt; t++) {
            const int kt = nkt - 1 - t;
            const int s0 = kt * 64;
            const int buf = t & 1;

            __syncthreads();                     // buf^1 consumers done
            if (t + 1 < nkt) load_kv(kt - 1, buf ^ 1);
            CP_COMMIT();
            CP_WAIT1();                          // current tile (and Q) resident
            __syncthreads();

            const uint32_t kb = sb + OFF_KV + (uint32_t)buf * KVBUF_B + klane;
            const uint32_t vb = sb + OFF_KV + (uint32_t)buf * KVBUF_B + vlane;

            // ---- S = Q K^T ----
            float sacc[8][4];
#pragma unroll
            for (int nf = 0; nf < 8; nf++)
#pragma unroll
                for (int d = 0; d < 4; d++) sacc[nf][d] = 0.f;

#pragma unroll
            for (int ks = 0; ks < 8; ks++) {
                uint32_t ah[4];
                LDSM_X4(ah[0], ah[1], ah[2], ah[3], qbase + ks * 32);
#pragma unroll
                for (int j = 0; j < 4; j++) {
                    uint32_t km[4];
                    LDSM_X4(km[0], km[1], km[2], km[3],
                            kb + j * (16 * QSTR) + ks * 32);
                    MMA_F16(sacc[2 * j],     ah, km[0], km[1]);
                    MMA_F16(sacc[2 * j + 1], ah, km[2], km[3]);
                }
            }

            // ---- bias + mask (log2 domain) ----
            const int row0 = q0 + WR + g;
            const int row1 = row0 + 8;
#pragma unroll
            for (int nf = 0; nf < 8; nf++) {
                const int cbase = s0 + nf * 8 + tg * 2;
#pragma unroll
                for (int e = 0; e < 2; e++) {
                    const int col = cbase + e;
                    float v0 = fmaf(sacc[nf][e], scale2, slope2 * (float)(col - row0));
                    float v1 = fmaf(sacc[nf][2 + e], scale2, slope2 * (float)(col - row1));
                    sacc[nf][e]     = (col > row0) ? -1e30f : v0;
                    sacc[nf][2 + e] = (col > row1) ? -1e30f : v1;
                }
            }

            // ---- online max; rescale only if max moved ----
            float m_new[2], alpha[2];
#pragma unroll
            for (int half = 0; half < 2; half++) {
                float mx = -1e30f;
#pragma unroll
                for (int nf = 0; nf < 8; nf++)
                    mx = fmaxf(mx, fmaxf(sacc[nf][2 * half], sacc[nf][2 * half + 1]));
                mx = fmaxf(mx, __shfl_xor_sync(0xffffffffu, mx, 1));
                mx = fmaxf(mx, __shfl_xor_sync(0xffffffffu, mx, 2));
                m_new[half] = fmaxf(m_run[half], mx);
                alpha[half] = exp2f(m_run[half] - m_new[half]);
                m_run[half] = m_new[half];
            }
            const bool upd = (alpha[0] < 1.f) || (alpha[1] < 1.f);
            if (__any_sync(0xffffffffu, upd)) {
#pragma unroll
                for (int nf = 0; nf < 16; nf++) {
                    oacc[nf][0] *= alpha[0]; oacc[nf][1] *= alpha[0];
                    oacc[nf][2] *= alpha[1]; oacc[nf][3] *= alpha[1];
                }
                lacc[0] *= alpha[0]; lacc[1] *= alpha[0];
                lacc[2] *= alpha[1]; lacc[3] *= alpha[1];
            }

            // ---- P = exp2(S - m) as fp16x2 fragments ----
            uint32_t ph[8][2];
#pragma unroll
            for (int nf = 0; nf < 8; nf++) {
                ph[nf][0] = ex2h2(sacc[nf][0] - m_new[0], sacc[nf][1] - m_new[0]);
                ph[nf][1] = ex2h2(sacc[nf][2] - m_new[1], sacc[nf][3] - m_new[1]);
            }

            // ---- O += P V (V via ldmatrix.trans) + ones-MMA row sums ----
#pragma unroll
            for (int ks = 0; ks < 4; ks++) {
                uint32_t ap[4] = {ph[2 * ks][0], ph[2 * ks][1],
                                  ph[2 * ks + 1][0], ph[2 * ks + 1][1]};
                MMA_F16(lacc, ap, ONESH2, ONESH2);
#pragma unroll
                for (int j = 0; j < 8; j++) {
                    uint32_t vm[4];
                    LDSM_X4_T(vm[0], vm[1], vm[2], vm[3],
                              vb + ks * (16 * QSTR) + j * 32);
                    MMA_F16(oacc[2 * j],     ap, vm[0], vm[1]);
                    MMA_F16(oacc[2 * j + 1], ap, vm[2], vm[3]);
                }
            }
        }

        // ---- normalize + write single fp16 O into g_A ----
        const float inv0 = 1.f / lacc[0];
        const float inv1 = 1.f / lacc[2];
#pragma unroll
        for (int nf = 0; nf < 16; nf++) {
            const int d0 = nf * 8 + tg * 2;
            {
                const int m = b * SEQ + q0 + WR + g;
                *(uint32_t*)(g_A + (size_t)m * HID + h * HD + d0) =
                    f2h2(oacc[nf][0] * inv0, oacc[nf][1] * inv0);
            }
            {
                const int m = b * SEQ + q0 + WR + g + 8;
                *(uint32_t*)(g_A + (size_t)m * HID + h * HD + d0) =
                    f2h2(oacc[nf][2] * inv1, oacc[nf][3] * inv1);
            }
        }
        __syncthreads();   // smem (Q + KV bufs) safe to reuse for next item
    }
}

// ---------------------------------------------------------------------------
extern "C" void kernel_launch(void* const* d_in, const int* in_sizes, int n_in,
                              void* d_out, int out_size)
{
    const float* hidden = (const float*)d_in[0];
    const float* w_qkv  = (const float*)d_in[1];
    const float* b_qkv  = (const float*)d_in[2];
    const float* w_proj = (const float*)d_in[3];
    const float* b_proj = (const float*)d_in[4];
    float* out = (float*)d_out;

    void *pA, *pWq, *pWp;
    cudaGetSymbolAddress(&pA, g_A);
    cudaGetSymbolAddress(&pWq, g_Wq);
    cudaGetSymbolAddress(&pWp, g_Wp);

    cudaFuncSetAttribute(mma_gemm_kernel,
                         cudaFuncAttributeMaxDynamicSharedMemorySize, GEMM_SMEM);
    cudaFuncSetAttribute(attn_mma_kernel,
                         cudaFuncAttributeMaxDynamicSharedMemorySize, ATT_SMEM);

    // weight conversion (transpose, single fp16)
    convert_w_kernel<<<dim3(3 * HID / 32, HID / 32), dim3(32, 8)>>>(
        w_qkv, (__half*)pWq, HID, 3 * HID);
    convert_w_kernel<<<dim3(HID / 32, HID / 32), dim3(32, 8)>>>(
        w_proj, (__half*)pWp, HID, HID);

    // hidden -> fp16 (QKV GEMM A input)
    {
        int n4 = MTOT * HID / 4;
        convert_h_kernel<<<(n4 + 255) / 256, 256>>>(hidden, (__half*)pA, n4);
    }

    // QKV GEMM -> Q, K, V (fp16, row-major)
    mma_gemm_kernel<<<dim3(3 * HID / 64, MTOT / 128), 128, GEMM_SMEM>>>(
        (const __half*)pA, (const __half*)pWq, b_qkv, nullptr, 3 * HID, 1);

    // balanced, double-buffered tensor-core flash attention -> g_A (fp16)
    attn_mma_kernel<<<NITEMS / 2, 256, ATT_SMEM>>>();

    // proj GEMM -> out
    mma_gemm_kernel<<<dim3(HID / 64, MTOT / 128), 128, GEMM_SMEM>>>(
        (const __half*)pA, (const __half*)pWp, b_proj, out, HID, 0);
}

// round 17
// speedup vs baseline: 1.8262x; 1.0385x over previous
#include <cuda_runtime.h>
#include <cuda_fp16.h>
#include <cstdint>

#define NH    16
#define HD    128
#define SEQ   2048
#define BATCH 2
#define HID   2048
#define MTOT  (BATCH * SEQ)   // 4096
#define GK    2048
#define LOG2E 1.4426950408889634f

// ---------------------------------------------------------------------------
// Scratch (__device__ globals — allocation-free)
// ---------------------------------------------------------------------------
__device__ __half g_Q[(size_t)BATCH * NH * SEQ * HD];  // Q [b,h,s,d]
__device__ __half g_K[(size_t)BATCH * NH * SEQ * HD];  // K [b,h,s,d]
__device__ __half g_V[(size_t)BATCH * NH * SEQ * HD];  // V [b,h,s,d]

__device__ __half g_A [(size_t)MTOT * HID];      // GEMM A (hidden / attn-out)
__device__ __half g_Wq[(size_t)3 * HID * HID];   // w_qkv^T fp16 [N,K]
__device__ __half g_Wp[(size_t)HID * HID];       // w_proj^T fp16 [N,K]

// ---------------------------------------------------------------------------
// helpers
// ---------------------------------------------------------------------------
__device__ __forceinline__ uint32_t smem_u32(const void* p) {
    uint32_t a;
    asm("{ .reg .u64 t; cvta.to.shared.u64 t, %1; cvt.u32.u64 %0, t; }"
        : "=r"(a) : "l"(p));
    return a;
}
__device__ __forceinline__ void cp_async16(uint32_t dst, const void* src) {
    asm volatile("cp.async.cg.shared.global [%0], [%1], 16;\n"
                 :: "r"(dst), "l"(src));
}
#define CP_COMMIT() asm volatile("cp.async.commit_group;\n" ::: "memory")
#define CP_WAIT1()  asm volatile("cp.async.wait_group 1;\n" ::: "memory")

#define LDSM_X4(r0, r1, r2, r3, addr)                                        \
    asm volatile("ldmatrix.sync.aligned.m8n8.x4.shared.b16 {%0,%1,%2,%3}, [%4];" \
                 : "=r"(r0), "=r"(r1), "=r"(r2), "=r"(r3) : "r"(addr))

#define LDSM_X4_T(r0, r1, r2, r3, addr)                                      \
    asm volatile("ldmatrix.sync.aligned.m8n8.x4.trans.shared.b16 {%0,%1,%2,%3}, [%4];" \
                 : "=r"(r0), "=r"(r1), "=r"(r2), "=r"(r3) : "r"(addr))

#define MMA_F16(d, a, b0, b1)                                                \
    asm volatile("mma.sync.aligned.m16n8k16.row.col.f32.f16.f16.f32 "        \
                 "{%0,%1,%2,%3}, {%4,%5,%6,%7}, {%8,%9}, {%0,%1,%2,%3};"     \
                 : "+f"((d)[0]), "+f"((d)[1]), "+f"((d)[2]), "+f"((d)[3])    \
                 : "r"((a)[0]), "r"((a)[1]), "r"((a)[2]), "r"((a)[3]),       \
                   "r"(b0), "r"(b1))

__device__ __forceinline__ uint32_t f2h2(float a, float b) {
    __half2 t = __floats2half2_rn(a, b);
    return *reinterpret_cast<uint32_t*>(&t);
}
__device__ __forceinline__ uint32_t ex2h2(float a, float b) {
    uint32_t x = f2h2(a, b), r;
    asm("ex2.approx.f16x2 %0, %1;" : "=r"(r) : "r"(x));
    return r;
}

// ---------------------------------------------------------------------------
// Conversion kernels
// ---------------------------------------------------------------------------
__global__ void convert_h_kernel(const float* __restrict__ in,
                                 __half* __restrict__ out, int n4)
{
    int i = blockIdx.x * blockDim.x + threadIdx.x;
    if (i >= n4) return;
    float4 x = ((const float4*)in)[i];
    ((uint2*)out)[i] = make_uint2(f2h2(x.x, x.y), f2h2(x.z, x.w));
}

// W[K,N] fp32 -> Wt[N,K] fp16 (tiled transpose)
__global__ void convert_w_kernel(const float* __restrict__ W,
                                 __half* __restrict__ out, int K, int N)
{
    __shared__ float t[32][33];
    int n0 = blockIdx.x * 32, k0 = blockIdx.y * 32;
    int tx = threadIdx.x, ty = threadIdx.y;  // 32 x 8
#pragma unroll
    for (int r = 0; r < 4; r++)
        t[ty + r * 8][tx] = W[(size_t)(k0 + ty + r * 8) * N + n0 + tx];
    __syncthreads();
#pragma unroll
    for (int r = 0; r < 4; r++) {
        float x = t[tx][ty + r * 8];
        out[(size_t)(n0 + ty + r * 8) * K + k0 + tx] = __float2half_rn(x);
    }
}

// ---------------------------------------------------------------------------
// mma.sync fp16 GEMM (single-A), XOR-swizzled smem, K-chunk 64.
// CTA tile 128x64, 128 threads (4 warps, 2x2 of 64x32) -> 4 CTAs/SM.
// R10-proven 2-stage pipeline order (do NOT reorder):
//   sync -> load(c+1) -> commit -> wait1 -> sync -> compute(c)
// mode 0: fp32 C out.  mode 1: QKV -> Q, K, V (all row-major fp16).
// ---------------------------------------------------------------------------
#define KC       64
#define NCH      (GK / KC)           // 32
#define ATILE_B  (128 * 128)         // 16384
#define BTILE_B  (64 * 128)          // 8192
#define STAGE_B  (ATILE_B + BTILE_B) // 24576
#define GEMM_SMEM (2 * STAGE_B)      // 49152 -> 4 CTAs/SM

__global__ void __launch_bounds__(128, 4) mma_gemm_kernel(
    const __half* __restrict__ A, const __half* __restrict__ B,
    const float* __restrict__ bias, float* __restrict__ C, int N, int mode)
{
    extern __shared__ char smem[];
    const uint32_t sb = smem_u32(smem);
    const int tid = threadIdx.x;
    const int wid = tid >> 5, lane = tid & 31;
    const int n0 = blockIdx.x * 64, m0 = blockIdx.y * 128;
    const int wm = (wid & 1) * 64, wn = (wid >> 1) * 32;

    const uint32_t swx = (uint32_t)(lane & 7) << 4;
    const uint32_t arow = (uint32_t)(wm + (lane & 15)) * 128;
    const uint32_t acol = ((uint32_t)(lane >> 4) << 4);
    const uint32_t brow = (uint32_t)(wn + (lane & 7) + ((lane >> 4) << 3)) * 128;
    const uint32_t bcol = (((uint32_t)(lane >> 3) & 1) << 4);

    float acc[4][4][4];
#pragma unroll
    for (int mi = 0; mi < 4; mi++)
#pragma unroll
        for (int nj = 0; nj < 4; nj++)
#pragma unroll
            for (int d = 0; d < 4; d++) acc[mi][nj][d] = 0.f;

    auto load_chunk = [&](int c, int buf) {
        const int kk = c * KC;
        const uint32_t st = sb + buf * STAGE_B;
#pragma unroll
        for (int i = 0; i < 8; i++) {
            int flat = tid + i * 128;
            int r = flat >> 3;
            int s = (flat & 7) * 16;
            uint32_t off = (uint32_t)r * 128 + (s ^ ((r & 7) << 4));
            cp_async16(st + off,
                       (const char*)(A + (size_t)(m0 + r) * GK + kk) + s);
        }
#pragma unroll
        for (int i = 0; i < 4; i++) {
            int flat = tid + i * 128;
            int r = flat >> 3;
            int s = (flat & 7) * 16;
            uint32_t off = (uint32_t)r * 128 + (s ^ ((r & 7) << 4));
            cp_async16(st + ATILE_B + off,
                       (const char*)(B + (size_t)(n0 + r) * GK + kk) + s);
        }
    };

    load_chunk(0, 0); CP_COMMIT();

    for (int c = 0; c < NCH; c++) {
        const int buf = c & 1;
        __syncthreads();
        if (c + 1 < NCH) load_chunk(c + 1, buf ^ 1);
        CP_COMMIT();
        CP_WAIT1();
        __syncthreads();

        const uint32_t sA = sb + buf * STAGE_B;
        const uint32_t sB = sA + ATILE_B;
#pragma unroll
        for (int ks = 0; ks < 4; ks++) {
            const uint32_t kc = (uint32_t)ks * 32;
            uint32_t b2[2][4];
#pragma unroll
            for (int p = 0; p < 2; p++)
                LDSM_X4(b2[p][0], b2[p][1], b2[p][2], b2[p][3],
                        sB + brow + p * (16 * 128) + ((bcol + kc) ^ swx));
#pragma unroll
            for (int mi = 0; mi < 4; mi++) {
                uint32_t a4[4];
                LDSM_X4(a4[0], a4[1], a4[2], a4[3],
                        sA + arow + mi * (16 * 128) + ((acol + kc) ^ swx));
#pragma unroll
                for (int nj = 0; nj < 4; nj++) {
                    const int p = nj >> 1, e = (nj & 1) * 2;
                    MMA_F16(acc[mi][nj], a4, b2[p][e], b2[p][e + 1]);
                }
            }
        }
    }

    // ---- epilogue (bias hoisted: 8 values per thread, loaded once) ----
    const int g = lane >> 2, tg = lane & 3;
    float bv[4][2];
#pragma unroll
    for (int nj = 0; nj < 4; nj++) {
        const int col = n0 + wn + nj * 8 + tg * 2;
        bv[nj][0] = __ldg(&bias[col]);
        bv[nj][1] = __ldg(&bias[col + 1]);
    }
#pragma unroll
    for (int mi = 0; mi < 4; mi++) {
#pragma unroll
        for (int half = 0; half < 2; half++) {
            const int m = m0 + wm + mi * 16 + g + half * 8;
            const int bb = m >> 11, s = m & (SEQ - 1);
#pragma unroll
            for (int nj = 0; nj < 4; nj++) {
                const int col = n0 + wn + nj * 8 + tg * 2;
                float v0 = acc[mi][nj][half * 2 + 0] + bv[nj][0];
                float v1 = acc[mi][nj][half * 2 + 1] + bv[nj][1];
                if (mode == 0) {
                    *(float2*)(C + (size_t)m * N + col) = make_float2(v0, v1);
                } else {
                    const int part = col >> 11;
                    const int h = (col >> 7) & (NH - 1);
                    const int d0 = col & (HD - 1);
                    const size_t idx = (((size_t)bb * NH + h) * SEQ + s) * HD + d0;
                    __half* dst = (part == 0) ? g_Q : (part == 1) ? g_K : g_V;
                    *(uint32_t*)(dst + idx) = f2h2(v0, v1);
                }
            }
        }
    }
}

// ---------------------------------------------------------------------------
// Tensor-core flash attention: causal + ALiBi log2, fp16 P via ex2.f16x2,
// single-product PV (V via ldmatrix.trans), ones-MMA row sums, descending
// k-tiles, double-buffered K/V, mask applied ONLY on the 2 diagonal tiles.
// 288-bin balanced mapping: group g = blockIdx/32, (h,b) = blockIdx%32.
//   g==0: single item qt=15 (32 tile-units)
//   g==1: single item qt=14 (30 units)
//   g>=2: pair qt=15-g then qt=g-2 (30 units)  -> all bins 30-32 units.
// Output written as single fp16 into g_A (proj input).
// ---------------------------------------------------------------------------
#define QSTR 272
#define OFF_KV (128 * QSTR)
#define KVBUF_B (128 * QSTR)
#define ATT_SMEM (OFF_KV + 2 * KVBUF_B)  // 104448 -> 2 CTAs/SM
#define ONESH2 0x3C003C00u
#define NBINS 288

__global__ void __launch_bounds__(256, 2) attn_mma_kernel()
{
    extern __shared__ char smc[];
    const uint32_t sb = smem_u32(smc);
    const int tid = threadIdx.x;
    const int wid = tid >> 5, lane = tid & 31;
    const int g = lane >> 2, tg = lane & 3;
    const int WR = wid * 16;

    const int grp = (int)blockIdx.x >> 5;
    const int r   = (int)blockIdx.x & 31;
    const int h   = r >> 1;
    const int b   = r & 1;
    const size_t bh = (size_t)b * NH + h;
    const int nsel = (grp < 2) ? 1 : 2;

    const uint32_t qbase = sb + (uint32_t)(WR + (lane & 15)) * QSTR + ((lane >> 4) << 4);
    const uint32_t klane = (uint32_t)((lane & 7) + ((lane >> 4) << 3)) * QSTR
                         + (((lane >> 3) & 1) << 4);
    const uint32_t vlane = (uint32_t)(64 * QSTR)
                         + (uint32_t)((lane & 7) + (((lane >> 3) & 1) << 3)) * QSTR
                         + ((lane >> 4) << 4);

    const float scale2 = (1.f / 128.f) * LOG2E;
    const float slope2 = exp2f(-0.5f * (float)(h + 1)) * LOG2E;

#pragma unroll 1
    for (int sel = 0; sel < nsel; sel++) {
        const int qt = (grp == 0) ? 15 : (grp == 1) ? 14
                      : (sel == 0) ? (15 - grp) : (grp - 2);
        const int q0 = qt * 128;
        const int nkt = 2 * qt + 2;

        auto load_kv = [&](int kt, int buf) {
            const int s0 = kt * 64;
            const uint32_t base = sb + OFF_KV + (uint32_t)buf * KVBUF_B;
            const __half* K = g_K + (bh * SEQ + s0) * HD;
            const __half* V = g_V + (bh * SEQ + s0) * HD;
#pragma unroll
            for (int i = 0; i < 4; i++) {
                int flat = tid + i * 256;
                int rr = flat >> 4, cb = (flat & 15) * 16;
                cp_async16(base + rr * QSTR + cb,
                           (const char*)(K + (size_t)rr * HD) + cb);
            }
#pragma unroll
            for (int i = 0; i < 4; i++) {
                int flat = tid + i * 256;
                int rr = flat >> 4, cb = (flat & 15) * 16;
                cp_async16(base + 64 * QSTR + rr * QSTR + cb,
                           (const char*)(V + (size_t)rr * HD) + cb);
            }
        };

        // ---- stage Q + first KV tile (descending: diagonal first) ----
        {
            const __half* Q = g_Q + (bh * SEQ + q0) * HD;
#pragma unroll
            for (int i = 0; i < 8; i++) {
                int flat = tid + i * 256;
                int rr = flat >> 4, cb = (flat & 15) * 16;
                cp_async16(sb + rr * QSTR + cb,
                           (const char*)(Q + (size_t)rr * HD) + cb);
            }
            CP_COMMIT();
        }
        load_kv(nkt - 1, 0);
        CP_COMMIT();

        float oacc[16][4];
#pragma unroll
        for (int nf = 0; nf < 16; nf++)
#pragma unroll
            for (int d = 0; d < 4; d++) oacc[nf][d] = 0.f;
        float lacc[4] = {0.f, 0.f, 0.f, 0.f};
        float m_run[2] = {-1e30f, -1e30f};

        for (int t = 0; t < nkt; t++) {
            const int kt = nkt - 1 - t;
            const int s0 = kt * 64;
            const int buf = t & 1;

            __syncthreads();
            if (t + 1 < nkt) load_kv(kt - 1, buf ^ 1);
            CP_COMMIT();
            CP_WAIT1();
            __syncthreads();

            const uint32_t kb = sb + OFF_KV + (uint32_t)buf * KVBUF_B + klane;
            const uint32_t vb = sb + OFF_KV + (uint32_t)buf * KVBUF_B + vlane;

            // ---- S = Q K^T ----
            float sacc[8][4];
#pragma unroll
            for (int nf = 0; nf < 8; nf++)
#pragma unroll
                for (int d = 0; d < 4; d++) sacc[nf][d] = 0.f;

#pragma unroll
            for (int ks = 0; ks < 8; ks++) {
                uint32_t ah[4];
                LDSM_X4(ah[0], ah[1], ah[2], ah[3], qbase + ks * 32);
#pragma unroll
                for (int j = 0; j < 4; j++) {
                    uint32_t km[4];
                    LDSM_X4(km[0], km[1], km[2], km[3],
                            kb + j * (16 * QSTR) + ks * 32);
                    MMA_F16(sacc[2 * j],     ah, km[0], km[1]);
                    MMA_F16(sacc[2 * j + 1], ah, km[2], km[3]);
                }
            }

            // ---- bias (+ mask only on the 2 diagonal tiles) ----
            const int row0 = q0 + WR + g;
            const int row1 = row0 + 8;
            if (t < 2) {
#pragma unroll
                for (int nf = 0; nf < 8; nf++) {
                    const int cbase = s0 + nf * 8 + tg * 2;
#pragma unroll
                    for (int e = 0; e < 2; e++) {
                        const int col = cbase + e;
                        float v0 = fmaf(sacc[nf][e], scale2, slope2 * (float)(col - row0));
                        float v1 = fmaf(sacc[nf][2 + e], scale2, slope2 * (float)(col - row1));
                        sacc[nf][e]     = (col > row0) ? -1e30f : v0;
                        sacc[nf][2 + e] = (col > row1) ? -1e30f : v1;
                    }
                }
            } else {
#pragma unroll
                for (int nf = 0; nf < 8; nf++) {
                    const int cbase = s0 + nf * 8 + tg * 2;
#pragma unroll
                    for (int e = 0; e < 2; e++) {
                        const int col = cbase + e;
                        sacc[nf][e]     = fmaf(sacc[nf][e], scale2,
                                               slope2 * (float)(col - row0));
                        sacc[nf][2 + e] = fmaf(sacc[nf][2 + e], scale2,
                                               slope2 * (float)(col - row1));
                    }
                }
            }

            // ---- online max; rescale only if max moved ----
            float m_new[2], alpha[2];
#pragma unroll
            for (int half = 0; half < 2; half++) {
                float mx = -1e30f;
#pragma unroll
                for (int nf = 0; nf < 8; nf++)
                    mx = fmaxf(mx, fmaxf(sacc[nf][2 * half], sacc[nf][2 * half + 1]));
                mx = fmaxf(mx, __shfl_xor_sync(0xffffffffu, mx, 1));
                mx = fmaxf(mx, __shfl_xor_sync(0xffffffffu, mx, 2));
                m_new[half] = fmaxf(m_run[half], mx);
                alpha[half] = exp2f(m_run[half] - m_new[half]);
                m_run[half] = m_new[half];
            }
            const bool upd = (alpha[0] < 1.f) || (alpha[1] < 1.f);
            if (__any_sync(0xffffffffu, upd)) {
#pragma unroll
                for (int nf = 0; nf < 16; nf++) {
                    oacc[nf][0] *= alpha[0]; oacc[nf][1] *= alpha[0];
                    oacc[nf][2] *= alpha[1]; oacc[nf][3] *= alpha[1];
                }
                lacc[0] *= alpha[0]; lacc[1] *= alpha[0];
                lacc[2] *= alpha[1]; lacc[3] *= alpha[1];
            }

            // ---- P = exp2(S - m) as fp16x2 fragments ----
            uint32_t ph[8][2];
#pragma unroll
            for (int nf = 0; nf < 8; nf++) {
                ph[nf][0] = ex2h2(sacc[nf][0] - m_new[0], sacc[nf][1] - m_new[0]);
                ph[nf][1] = ex2h2(sacc[nf][2] - m_new[1], sacc[nf][3] - m_new[1]);
            }

            // ---- O += P V (V via ldmatrix.trans) + ones-MMA row sums ----
#pragma unroll
            for (int ks = 0; ks < 4; ks++) {
                uint32_t ap[4] = {ph[2 * ks][0], ph[2 * ks][1],
                                  ph[2 * ks + 1][0], ph[2 * ks + 1][1]};
                MMA_F16(lacc, ap, ONESH2, ONESH2);
#pragma unroll
                for (int j = 0; j < 8; j++) {
                    uint32_t vm[4];
                    LDSM_X4_T(vm[0], vm[1], vm[2], vm[3],
                              vb + ks * (16 * QSTR) + j * 32);
                    MMA_F16(oacc[2 * j],     ap, vm[0], vm[1]);
                    MMA_F16(oacc[2 * j + 1], ap, vm[2], vm[3]);
                }
            }
        }

        // ---- normalize + write single fp16 O into g_A ----
        const float inv0 = 1.f / lacc[0];
        const float inv1 = 1.f / lacc[2];
#pragma unroll
        for (int nf = 0; nf < 16; nf++) {
            const int d0 = nf * 8 + tg * 2;
            {
                const int m = b * SEQ + q0 + WR + g;
                *(uint32_t*)(g_A + (size_t)m * HID + h * HD + d0) =
                    f2h2(oacc[nf][0] * inv0, oacc[nf][1] * inv0);
            }
            {
                const int m = b * SEQ + q0 + WR + g + 8;
                *(uint32_t*)(g_A + (size_t)m * HID + h * HD + d0) =
                    f2h2(oacc[nf][2] * inv1, oacc[nf][3] * inv1);
            }
        }
        __syncthreads();   // smem safe to reuse for next item
    }
}

// ---------------------------------------------------------------------------
extern "C" void kernel_launch(void* const* d_in, const int* in_sizes, int n_in,
                              void* d_out, int out_size)
{
    const float* hidden = (const float*)d_in[0];
    const float* w_qkv  = (const float*)d_in[1];
    const float* b_qkv  = (const float*)d_in[2];
    const float* w_proj = (const float*)d_in[3];
    const float* b_proj = (const float*)d_in[4];
    float* out = (float*)d_out;

    void *pA, *pWq, *pWp;
    cudaGetSymbolAddress(&pA, g_A);
    cudaGetSymbolAddress(&pWq, g_Wq);
    cudaGetSymbolAddress(&pWp, g_Wp);

    cudaFuncSetAttribute(mma_gemm_kernel,
                         cudaFuncAttributeMaxDynamicSharedMemorySize, GEMM_SMEM);
    cudaFuncSetAttribute(attn_mma_kernel,
                         cudaFuncAttributeMaxDynamicSharedMemorySize, ATT_SMEM);

    // weight conversion (transpose, single fp16)
    convert_w_kernel<<<dim3(3 * HID / 32, HID / 32), dim3(32, 8)>>>(
        w_qkv, (__half*)pWq, HID, 3 * HID);
    convert_w_kernel<<<dim3(HID / 32, HID / 32), dim3(32, 8)>>>(
        w_proj, (__half*)pWp, HID, HID);

    // hidden -> fp16 (QKV GEMM A input)
    {
        int n4 = MTOT * HID / 4;
        convert_h_kernel<<<(n4 + 255) / 256, 256>>>(hidden, (__half*)pA, n4);
    }

    // QKV GEMM -> Q, K, V (fp16, row-major)
    mma_gemm_kernel<<<dim3(3 * HID / 64, MTOT / 128), 128, GEMM_SMEM>>>(
        (const __half*)pA, (const __half*)pWq, b_qkv, nullptr, 3 * HID, 1);

    // 288-bin balanced, double-buffered flash attention -> g_A (fp16)
    attn_mma_kernel<<<NBINS, 256, ATT_SMEM>>>();

    // proj GEMM -> out
    mma_gemm_kernel<<<dim3(HID / 64, MTOT / 128), 128, GEMM_SMEM>>>(
        (const __half*)pA, (const __half*)pWp, b_proj, out, HID, 0);
}